// round 14
// baseline (speedup 1.0000x reference)
#include <cuda_runtime.h>
#include <cuda_bf16.h>
#include <cuda_fp16.h>
#include <cstdint>
#include <math.h>

// ---------------- static scratch (no allocs allowed) ----------------
#define NMAX 50176
#define EMAX 1700000

__device__ __half g_h1f[NMAX * 256];          // x @ W1 (fp16, for agg1 gather)
__device__ __nv_bfloat16 g_h1ah[NMAX * 256], g_h1al[NMAX * 256]; // layer1 out, bf16 split
__device__ __half g_h2f[NMAX * 40];           // fp16 for agg2 gather
__device__ float g_as1[NMAX * 4], g_ad1[NMAX * 4];
__device__ float g_as2[NMAX],     g_ad2[NMAX];
__device__ int   g_deg[NMAX], g_off[NMAX + 1], g_cur[NMAX];
__device__ int   g_csr[EMAX];
__device__ int   g_is64;
// bf16 split operands for tensor-core GEMMs
__device__ __nv_bfloat16 g_wh[256 * 256],  g_wl[256 * 256];
__device__ __nv_bfloat16 g_w2h[256 * 64],  g_w2l[256 * 64];   // W2 padded 40->64

// ---------------- PTX helpers ----------------
__device__ __forceinline__ unsigned smem_u32(const void* p) {
    return (unsigned)__cvta_generic_to_shared(p);
}
__device__ __forceinline__ void ldsm_x4(unsigned addr, unsigned& r0, unsigned& r1, unsigned& r2, unsigned& r3) {
    asm volatile("ldmatrix.sync.aligned.m8n8.x4.shared.b16 {%0,%1,%2,%3},[%4];"
                 : "=r"(r0), "=r"(r1), "=r"(r2), "=r"(r3) : "r"(addr));
}
__device__ __forceinline__ void ldsm_x4t(unsigned addr, unsigned& r0, unsigned& r1, unsigned& r2, unsigned& r3) {
    asm volatile("ldmatrix.sync.aligned.m8n8.x4.trans.shared.b16 {%0,%1,%2,%3},[%4];"
                 : "=r"(r0), "=r"(r1), "=r"(r2), "=r"(r3) : "r"(addr));
}
__device__ __forceinline__ void mma_bf16(float* c, unsigned a0, unsigned a1, unsigned a2, unsigned a3,
                                         unsigned b0, unsigned b1) {
    asm volatile("mma.sync.aligned.m16n8k16.row.col.f32.bf16.bf16.f32 "
                 "{%0,%1,%2,%3},{%4,%5,%6,%7},{%8,%9},{%0,%1,%2,%3};"
                 : "+f"(c[0]), "+f"(c[1]), "+f"(c[2]), "+f"(c[3])
                 : "r"(a0), "r"(a1), "r"(a2), "r"(a3), "r"(b0), "r"(b1));
}

// ---------------- combined bf16 split: W1 (65536) + W2 padded (256x64) ----------------
__global__ void k_split_all(const float* __restrict__ W1, const float* __restrict__ W2) {
    int i = blockIdx.x * blockDim.x + threadIdx.x;
    if (i < 65536) {
        float v = W1[i];
        __nv_bfloat16 h = __float2bfloat16(v);
        g_wh[i] = h;
        g_wl[i] = __float2bfloat16(v - __bfloat162float(h));
    } else if (i < 65536 + 256 * 64) {
        int j = i - 65536;
        int r = j >> 6, c = j & 63;
        float v = (c < 40) ? W2[r * 40 + c] : 0.f;
        __nv_bfloat16 h = __float2bfloat16(v);
        g_w2h[j] = h;
        g_w2l[j] = __float2bfloat16(v - __bfloat162float(h));
    }
}

// ---------------- edge dtype detection + zero deg/as2/ad2 (fused) ----------------
__global__ void k_detect(const int* __restrict__ e32, int E, int N) {
    int i = blockIdx.x * blockDim.x + threadIdx.x;
    if (i < N) {
        g_deg[i] = 0;
        g_as2[i] = 0.f;
        g_ad2[i] = 0.f;
    }
    if (blockIdx.x == 0 && threadIdx.x < 32) {
        int lane = threadIdx.x;
        int nz = 0;
        for (int k = lane; k < 64; k += 32)
            if (k < E) nz |= (e32[2 * k + 1] != 0);
        unsigned b = __ballot_sync(0xffffffffu, nz);
        if (lane == 0) g_is64 = (b == 0u);
    }
}

__device__ __forceinline__ int edge_at(const void* edge, int is64, long long idx) {
    if (is64) return (int)((const long long*)edge)[idx];
    return ((const int*)edge)[idx];
}

// ---------------- CSR build ----------------
__global__ void k_count(const void* __restrict__ edge, int E, int N) {
    int e = blockIdx.x * blockDim.x + threadIdx.x;
    int ET = E + N;
    if (e >= ET) return;
    int is64 = g_is64;
    int dst = (e < E) ? edge_at(edge, is64, (long long)E + e) : (e - E);
    atomicAdd(&g_deg[dst], 1);
}

__global__ void __launch_bounds__(1024) k_scan_fused(int N) {
    __shared__ int s[1024];
    int t = threadIdx.x;
    int chunk = (N + 1023) >> 10;
    int base = t * chunk;
    int sum = 0;
    for (int i = 0; i < chunk; i++) {
        int idx = base + i;
        if (idx < N) sum += g_deg[idx];
    }
    s[t] = sum;
    __syncthreads();
    for (int o = 1; o < 1024; o <<= 1) {
        int v = (t >= o) ? s[t - o] : 0;
        __syncthreads();
        s[t] += v;
        __syncthreads();
    }
    int run = s[t] - sum;
    for (int i = 0; i < chunk; i++) {
        int idx = base + i;
        if (idx < N) {
            g_off[idx] = run;
            g_cur[idx] = run;
            run += g_deg[idx];
        }
    }
    if (t == 1023) g_off[N] = s[1023];
}

__global__ void k_scatter(const void* __restrict__ edge, int E, int N) {
    int e = blockIdx.x * blockDim.x + threadIdx.x;
    int ET = E + N;
    if (e >= ET) return;
    int src, dst;
    if (e < E) {
        int is64 = g_is64;
        src = edge_at(edge, is64, e);
        dst = edge_at(edge, is64, (long long)E + e);
    } else {
        src = dst = e - E;
    }
    int pos = atomicAdd(&g_cur[dst], 1);
    g_csr[pos] = src;
}

// ---------------- GEMM1: x fp32 loaded directly, split in-kernel; fused attn1 ----------------
#define LDA 40
#define LDB1 136
__global__ void __launch_bounds__(256, 2) k_gemm1_tc(const float* __restrict__ X, int M,
        const float* __restrict__ att_s, const float* __restrict__ att_d) {
    __shared__ __nv_bfloat16 Ah[128 * LDA], Al[128 * LDA];
    __shared__ __nv_bfloat16 Bh[32 * LDB1], Bl[32 * LDB1];
    int tid = threadIdx.x;
    int warp = tid >> 5, lane = tid & 31;
    int wm = warp & 3, wn = warp >> 2;
    int row0 = blockIdx.y * 128, col0 = blockIdx.x * 128;

    float acc[2][8][4];
#pragma unroll
    for (int mi = 0; mi < 2; mi++)
#pragma unroll
        for (int ni = 0; ni < 8; ni++)
#pragma unroll
            for (int k = 0; k < 4; k++) acc[mi][ni][k] = 0.f;

    int lrow = lane & 15, lcb = lane >> 4;

    for (int kt = 0; kt < 256; kt += 32) {
#pragma unroll
        for (int i = 0; i < 2; i++) {
            int v = tid + i * 256;
            int r = v >> 2, cv = (v & 3) * 8;
            int gr = row0 + r;
            float4 f0 = make_float4(0.f, 0.f, 0.f, 0.f), f1 = f0;
            if (gr < M) {
                f0 = *(const float4*)&X[(size_t)gr * 256 + kt + cv];
                f1 = *(const float4*)&X[(size_t)gr * 256 + kt + cv + 4];
            }
            float fv[8] = {f0.x, f0.y, f0.z, f0.w, f1.x, f1.y, f1.z, f1.w};
            __nv_bfloat16 hb[8], lb[8];
#pragma unroll
            for (int k = 0; k < 8; k++) {
                hb[k] = __float2bfloat16(fv[k]);
                lb[k] = __float2bfloat16(fv[k] - __bfloat162float(hb[k]));
            }
            *(uint4*)&Ah[r * LDA + cv] = *(const uint4*)hb;
            *(uint4*)&Al[r * LDA + cv] = *(const uint4*)lb;
        }
#pragma unroll
        for (int i = 0; i < 2; i++) {
            int v = tid + i * 256;
            int r = v >> 4, cv = (v & 15) * 8;
            *(uint4*)&Bh[r * LDB1 + cv] = *(const uint4*)&g_wh[(size_t)(kt + r) * 256 + col0 + cv];
            *(uint4*)&Bl[r * LDB1 + cv] = *(const uint4*)&g_wl[(size_t)(kt + r) * 256 + col0 + cv];
        }
        __syncthreads();

#pragma unroll
        for (int ks = 0; ks < 32; ks += 16) {
            unsigned ah[2][4], al[2][4], bh[4][4], bl[4][4];
#pragma unroll
            for (int mi = 0; mi < 2; mi++) {
                unsigned ad = smem_u32(&Ah[(wm * 32 + mi * 16 + lrow) * LDA + ks + lcb * 8]);
                ldsm_x4(ad, ah[mi][0], ah[mi][1], ah[mi][2], ah[mi][3]);
                unsigned ad2 = smem_u32(&Al[(wm * 32 + mi * 16 + lrow) * LDA + ks + lcb * 8]);
                ldsm_x4(ad2, al[mi][0], al[mi][1], al[mi][2], al[mi][3]);
            }
#pragma unroll
            for (int nj = 0; nj < 4; nj++) {
                unsigned bd = smem_u32(&Bh[(ks + lrow) * LDB1 + wn * 64 + nj * 16 + lcb * 8]);
                ldsm_x4t(bd, bh[nj][0], bh[nj][1], bh[nj][2], bh[nj][3]);
                unsigned bd2 = smem_u32(&Bl[(ks + lrow) * LDB1 + wn * 64 + nj * 16 + lcb * 8]);
                ldsm_x4t(bd2, bl[nj][0], bl[nj][1], bl[nj][2], bl[nj][3]);
            }
#pragma unroll
            for (int mi = 0; mi < 2; mi++)
#pragma unroll
                for (int ni = 0; ni < 8; ni++) {
                    int nj = ni >> 1, s2 = (ni & 1) * 2;
                    mma_bf16(acc[mi][ni], ah[mi][0], ah[mi][1], ah[mi][2], ah[mi][3],
                             bh[nj][s2], bh[nj][s2 + 1]);
                    mma_bf16(acc[mi][ni], ah[mi][0], ah[mi][1], ah[mi][2], ah[mi][3],
                             bl[nj][s2], bl[nj][s2 + 1]);
                    mma_bf16(acc[mi][ni], al[mi][0], al[mi][1], al[mi][2], al[mi][3],
                             bh[nj][s2], bh[nj][s2 + 1]);
                }
        }
        __syncthreads();
    }

    int tr = lane >> 2, tc = (lane & 3) * 2;
    int head = blockIdx.x * 2 + wn;
#pragma unroll
    for (int mi = 0; mi < 2; mi++) {
        float ps0 = 0.f, pd0 = 0.f, ps1 = 0.f, pd1 = 0.f;
#pragma unroll
        for (int ni = 0; ni < 8; ni++) {
            int r = row0 + wm * 32 + mi * 16 + tr;
            int c = col0 + wn * 64 + ni * 8 + tc;
            if (r < M)
                *(__half2*)&g_h1f[(size_t)r * 256 + c] = __floats2half2_rn(acc[mi][ni][0], acc[mi][ni][1]);
            if (r + 8 < M)
                *(__half2*)&g_h1f[(size_t)(r + 8) * 256 + c] = __floats2half2_rn(acc[mi][ni][2], acc[mi][ni][3]);
            float s0 = __ldg(&att_s[c]), s1 = __ldg(&att_s[c + 1]);
            float d0 = __ldg(&att_d[c]), d1 = __ldg(&att_d[c + 1]);
            ps0 = fmaf(acc[mi][ni][0], s0, ps0); ps0 = fmaf(acc[mi][ni][1], s1, ps0);
            pd0 = fmaf(acc[mi][ni][0], d0, pd0); pd0 = fmaf(acc[mi][ni][1], d1, pd0);
            ps1 = fmaf(acc[mi][ni][2], s0, ps1); ps1 = fmaf(acc[mi][ni][3], s1, ps1);
            pd1 = fmaf(acc[mi][ni][2], d0, pd1); pd1 = fmaf(acc[mi][ni][3], d1, pd1);
        }
        ps0 += __shfl_xor_sync(0xffffffffu, ps0, 1); ps0 += __shfl_xor_sync(0xffffffffu, ps0, 2);
        pd0 += __shfl_xor_sync(0xffffffffu, pd0, 1); pd0 += __shfl_xor_sync(0xffffffffu, pd0, 2);
        ps1 += __shfl_xor_sync(0xffffffffu, ps1, 1); ps1 += __shfl_xor_sync(0xffffffffu, ps1, 2);
        pd1 += __shfl_xor_sync(0xffffffffu, pd1, 1); pd1 += __shfl_xor_sync(0xffffffffu, pd1, 2);
        if ((lane & 3) == 0) {
            int r0 = row0 + wm * 32 + mi * 16 + tr;
            if (r0 < M)     { g_as1[r0 * 4 + head] = ps0; g_ad1[r0 * 4 + head] = pd0; }
            if (r0 + 8 < M) { g_as1[(r0 + 8) * 4 + head] = ps1; g_ad1[(r0 + 8) * 4 + head] = pd1; }
        }
    }
}

// ---------------- GEMM2 (tensor core): h2 = h1a @ W2pad, fused attn2 ----------------
#define LDB 72
__global__ void __launch_bounds__(256) k_gemm2_tc(int M,
        const float* __restrict__ att_s, const float* __restrict__ att_d) {
    __shared__ __nv_bfloat16 Ah[128 * LDA], Al[128 * LDA];
    __shared__ __nv_bfloat16 Bh[32 * LDB],  Bl[32 * LDB];
    int tid = threadIdx.x;
    int warp = tid >> 5, lane = tid & 31;
    int wm = warp & 3, wn = warp >> 2;
    int row0 = blockIdx.x * 128;

    float acc[2][4][4];
#pragma unroll
    for (int mi = 0; mi < 2; mi++)
#pragma unroll
        for (int ni = 0; ni < 4; ni++)
#pragma unroll
            for (int k = 0; k < 4; k++) acc[mi][ni][k] = 0.f;

    int lrow = lane & 15, lcb = lane >> 4;

    for (int kt = 0; kt < 256; kt += 32) {
#pragma unroll
        for (int i = 0; i < 2; i++) {
            int v = tid + i * 256;
            int r = v >> 2, cv = (v & 3) * 8;
            int gr = row0 + r;
            uint4 vh, vl;
            if (gr < M) {
                vh = *(const uint4*)&g_h1ah[(size_t)gr * 256 + kt + cv];
                vl = *(const uint4*)&g_h1al[(size_t)gr * 256 + kt + cv];
            } else { vh = make_uint4(0,0,0,0); vl = vh; }
            *(uint4*)&Ah[r * LDA + cv] = vh;
            *(uint4*)&Al[r * LDA + cv] = vl;
        }
        {
            int r = tid >> 3, cv = (tid & 7) * 8;
            *(uint4*)&Bh[r * LDB + cv] = *(const uint4*)&g_w2h[(size_t)(kt + r) * 64 + cv];
            *(uint4*)&Bl[r * LDB + cv] = *(const uint4*)&g_w2l[(size_t)(kt + r) * 64 + cv];
        }
        __syncthreads();

#pragma unroll
        for (int ks = 0; ks < 32; ks += 16) {
            unsigned ah[2][4], al[2][4], bh[2][4], bl[2][4];
#pragma unroll
            for (int mi = 0; mi < 2; mi++) {
                unsigned ad = smem_u32(&Ah[(wm * 32 + mi * 16 + lrow) * LDA + ks + lcb * 8]);
                ldsm_x4(ad, ah[mi][0], ah[mi][1], ah[mi][2], ah[mi][3]);
                unsigned ad2 = smem_u32(&Al[(wm * 32 + mi * 16 + lrow) * LDA + ks + lcb * 8]);
                ldsm_x4(ad2, al[mi][0], al[mi][1], al[mi][2], al[mi][3]);
            }
#pragma unroll
            for (int nj = 0; nj < 2; nj++) {
                unsigned bd = smem_u32(&Bh[(ks + lrow) * LDB + wn * 32 + nj * 16 + lcb * 8]);
                ldsm_x4t(bd, bh[nj][0], bh[nj][1], bh[nj][2], bh[nj][3]);
                unsigned bd2 = smem_u32(&Bl[(ks + lrow) * LDB + wn * 32 + nj * 16 + lcb * 8]);
                ldsm_x4t(bd2, bl[nj][0], bl[nj][1], bl[nj][2], bl[nj][3]);
            }
#pragma unroll
            for (int mi = 0; mi < 2; mi++)
#pragma unroll
                for (int ni = 0; ni < 4; ni++) {
                    int nj = ni >> 1, s2 = (ni & 1) * 2;
                    mma_bf16(acc[mi][ni], ah[mi][0], ah[mi][1], ah[mi][2], ah[mi][3],
                             bh[nj][s2], bh[nj][s2 + 1]);
                    mma_bf16(acc[mi][ni], ah[mi][0], ah[mi][1], ah[mi][2], ah[mi][3],
                             bl[nj][s2], bl[nj][s2 + 1]);
                    mma_bf16(acc[mi][ni], al[mi][0], al[mi][1], al[mi][2], al[mi][3],
                             bh[nj][s2], bh[nj][s2 + 1]);
                }
        }
        __syncthreads();
    }

    int tr = lane >> 2, tc = (lane & 3) * 2;
#pragma unroll
    for (int mi = 0; mi < 2; mi++) {
        float ps0 = 0.f, pd0 = 0.f, ps1 = 0.f, pd1 = 0.f;
#pragma unroll
        for (int ni = 0; ni < 4; ni++) {
            int r = row0 + wm * 32 + mi * 16 + tr;
            int c = wn * 32 + ni * 8 + tc;
            if (c < 40) {
                if (r < M)
                    *(__half2*)&g_h2f[(size_t)r * 40 + c] = __floats2half2_rn(acc[mi][ni][0], acc[mi][ni][1]);
                if (r + 8 < M)
                    *(__half2*)&g_h2f[(size_t)(r + 8) * 40 + c] = __floats2half2_rn(acc[mi][ni][2], acc[mi][ni][3]);
                float s0 = __ldg(&att_s[c]), s1 = __ldg(&att_s[c + 1]);
                float d0 = __ldg(&att_d[c]), d1 = __ldg(&att_d[c + 1]);
                ps0 = fmaf(acc[mi][ni][0], s0, ps0); ps0 = fmaf(acc[mi][ni][1], s1, ps0);
                pd0 = fmaf(acc[mi][ni][0], d0, pd0); pd0 = fmaf(acc[mi][ni][1], d1, pd0);
                ps1 = fmaf(acc[mi][ni][2], s0, ps1); ps1 = fmaf(acc[mi][ni][3], s1, ps1);
                pd1 = fmaf(acc[mi][ni][2], d0, pd1); pd1 = fmaf(acc[mi][ni][3], d1, pd1);
            }
        }
        ps0 += __shfl_xor_sync(0xffffffffu, ps0, 1); ps0 += __shfl_xor_sync(0xffffffffu, ps0, 2);
        pd0 += __shfl_xor_sync(0xffffffffu, pd0, 1); pd0 += __shfl_xor_sync(0xffffffffu, pd0, 2);
        ps1 += __shfl_xor_sync(0xffffffffu, ps1, 1); ps1 += __shfl_xor_sync(0xffffffffu, ps1, 2);
        pd1 += __shfl_xor_sync(0xffffffffu, pd1, 1); pd1 += __shfl_xor_sync(0xffffffffu, pd1, 2);
        if ((lane & 3) == 0) {
            int r0 = row0 + wm * 32 + mi * 16 + tr;
            if (r0 < M)     { atomicAdd(&g_as2[r0], ps0); atomicAdd(&g_ad2[r0], pd0); }
            if (r0 + 8 < M) { atomicAdd(&g_as2[r0 + 8], ps1); atomicAdd(&g_ad2[r0 + 8], pd1); }
        }
    }
}

// ---------------- agg1: 4-edge unroll, inline weights, fp16 gather, bias+ELU, bf16-split out ----------------
__global__ void k_agg1(const float* __restrict__ bias, int M) {
    int w = (blockIdx.x * blockDim.x + threadIdx.x) >> 5;
    int lane = threadIdx.x & 31;
    if (w >= M) return;
    int start = g_off[w], end = g_off[w + 1];
    int hh = lane >> 3;
    int c0 = lane * 8;
    float4 adv = *(const float4*)&g_ad1[w * 4];
    float adh = (hh == 0) ? adv.x : (hh == 1) ? adv.y : (hh == 2) ? adv.z : adv.w;

    float acc[8] = {0.f, 0.f, 0.f, 0.f, 0.f, 0.f, 0.f, 0.f};
    float denom = 0.f;
    int j = start;
    for (; j + 3 < end; j += 4) {
        int s0 = g_csr[j], s1 = g_csr[j + 1], s2 = g_csr[j + 2], s3 = g_csr[j + 3];
        float a0 = g_as1[s0 * 4 + hh], a1 = g_as1[s1 * 4 + hh];
        float a2 = g_as1[s2 * 4 + hh], a3 = g_as1[s3 * 4 + hh];
        uint4 q0 = *(const uint4*)&g_h1f[(size_t)s0 * 256 + c0];
        uint4 q1 = *(const uint4*)&g_h1f[(size_t)s1 * 256 + c0];
        uint4 q2 = *(const uint4*)&g_h1f[(size_t)s2 * 256 + c0];
        uint4 q3 = *(const uint4*)&g_h1f[(size_t)s3 * 256 + c0];
        float e0 = a0 + adh; e0 = e0 > 0.f ? e0 : 0.2f * e0;
        float e1 = a1 + adh; e1 = e1 > 0.f ? e1 : 0.2f * e1;
        float e2 = a2 + adh; e2 = e2 > 0.f ? e2 : 0.2f * e2;
        float e3 = a3 + adh; e3 = e3 > 0.f ? e3 : 0.2f * e3;
        float w0 = __expf(e0), w1 = __expf(e1), w2 = __expf(e2), w3 = __expf(e3);
        denom += (w0 + w1) + (w2 + w3);
        const __half2* p0 = (const __half2*)&q0;
        const __half2* p1 = (const __half2*)&q1;
        const __half2* p2 = (const __half2*)&q2;
        const __half2* p3 = (const __half2*)&q3;
#pragma unroll
        for (int k = 0; k < 4; k++) {
            float2 f0 = __half22float2(p0[k]);
            float2 f1 = __half22float2(p1[k]);
            float2 f2 = __half22float2(p2[k]);
            float2 f3 = __half22float2(p3[k]);
            acc[2*k]   = fmaf(w0, f0.x, acc[2*k]);   acc[2*k]   = fmaf(w1, f1.x, acc[2*k]);
            acc[2*k]   = fmaf(w2, f2.x, acc[2*k]);   acc[2*k]   = fmaf(w3, f3.x, acc[2*k]);
            acc[2*k+1] = fmaf(w0, f0.y, acc[2*k+1]); acc[2*k+1] = fmaf(w1, f1.y, acc[2*k+1]);
            acc[2*k+1] = fmaf(w2, f2.y, acc[2*k+1]); acc[2*k+1] = fmaf(w3, f3.y, acc[2*k+1]);
        }
    }
    for (; j < end; j++) {
        int s0 = g_csr[j];
        float e0 = g_as1[s0 * 4 + hh] + adh;
        e0 = e0 > 0.f ? e0 : 0.2f * e0;
        float w0 = __expf(e0);
        uint4 q0 = *(const uint4*)&g_h1f[(size_t)s0 * 256 + c0];
        denom += w0;
        const __half2* a = (const __half2*)&q0;
#pragma unroll
        for (int k = 0; k < 4; k++) {
            float2 fa = __half22float2(a[k]);
            acc[2*k]   = fmaf(w0, fa.x, acc[2*k]);
            acc[2*k+1] = fmaf(w0, fa.y, acc[2*k+1]);
        }
    }
    float inv = 1.f / denom;
    __nv_bfloat16 hi8[8], lo8[8];
#pragma unroll
    for (int k = 0; k < 8; k++) {
        float v = acc[k] * inv + bias[c0 + k];
        v = v > 0.f ? v : (__expf(v) - 1.f);   // ELU
        __nv_bfloat16 h = __float2bfloat16(v);
        hi8[k] = h;
        lo8[k] = __float2bfloat16(v - __bfloat162float(h));
    }
    *(uint4*)&g_h1ah[(size_t)w * 256 + c0] = *(const uint4*)hi8;
    *(uint4*)&g_h1al[(size_t)w * 256 + c0] = *(const uint4*)lo8;
}

// ---------------- agg2: 4-edge unroll, inline weights, fp16 gather, final output ----------------
__global__ void k_agg2(const float* __restrict__ b2, float* __restrict__ out, int M) {
    int w = (blockIdx.x * blockDim.x + threadIdx.x) >> 5;
    int lane = threadIdx.x & 31;
    if (w >= M) return;
    int start = g_off[w], end = g_off[w + 1];
    float adv = g_ad2[w];
    bool val = lane < 20;
    float denom = 0.f, acc0 = 0.f, acc1 = 0.f;
    int j = start;
    for (; j + 3 < end; j += 4) {
        int s0 = g_csr[j], s1 = g_csr[j + 1], s2 = g_csr[j + 2], s3 = g_csr[j + 3];
        float a0 = g_as2[s0], a1 = g_as2[s1], a2 = g_as2[s2], a3 = g_as2[s3];
        float2 f0 = make_float2(0.f, 0.f), f1 = f0, f2 = f0, f3 = f0;
        if (val) {
            f0 = __half22float2(*(const __half2*)&g_h2f[(size_t)s0 * 40 + lane * 2]);
            f1 = __half22float2(*(const __half2*)&g_h2f[(size_t)s1 * 40 + lane * 2]);
            f2 = __half22float2(*(const __half2*)&g_h2f[(size_t)s2 * 40 + lane * 2]);
            f3 = __half22float2(*(const __half2*)&g_h2f[(size_t)s3 * 40 + lane * 2]);
        }
        float e0 = a0 + adv; e0 = e0 > 0.f ? e0 : 0.2f * e0;
        float e1 = a1 + adv; e1 = e1 > 0.f ? e1 : 0.2f * e1;
        float e2 = a2 + adv; e2 = e2 > 0.f ? e2 : 0.2f * e2;
        float e3 = a3 + adv; e3 = e3 > 0.f ? e3 : 0.2f * e3;
        float w0 = __expf(e0), w1 = __expf(e1), w2 = __expf(e2), w3 = __expf(e3);
        denom += (w0 + w1) + (w2 + w3);
        acc0 = fmaf(w0, f0.x, acc0); acc0 = fmaf(w1, f1.x, acc0);
        acc0 = fmaf(w2, f2.x, acc0); acc0 = fmaf(w3, f3.x, acc0);
        acc1 = fmaf(w0, f0.y, acc1); acc1 = fmaf(w1, f1.y, acc1);
        acc1 = fmaf(w2, f2.y, acc1); acc1 = fmaf(w3, f3.y, acc1);
    }
    for (; j < end; j++) {
        int s0 = g_csr[j];
        float e0 = g_as2[s0] + adv;
        e0 = e0 > 0.f ? e0 : 0.2f * e0;
        float w0 = __expf(e0);
        float2 f0 = make_float2(0.f, 0.f);
        if (val) f0 = __half22float2(*(const __half2*)&g_h2f[(size_t)s0 * 40 + lane * 2]);
        denom += w0;
        acc0 = fmaf(w0, f0.x, acc0);
        acc1 = fmaf(w0, f0.y, acc1);
    }
    float inv = 1.f / denom;
    if (val) {
        out[(size_t)w * 40 + lane * 2]     = acc0 * inv + __ldg(&b2[lane * 2]);
        out[(size_t)w * 40 + lane * 2 + 1] = acc1 * inv + __ldg(&b2[lane * 2 + 1]);
    }
}

// ---------------- launch ----------------
extern "C" void kernel_launch(void* const* d_in, const int* in_sizes, int n_in,
                              void* d_out, int out_size) {
    const float* x    = (const float*)d_in[0];
    const void*  edge = (const void*)d_in[1];
    const float* W1   = (const float*)d_in[2];
    const float* as1  = (const float*)d_in[3];
    const float* ad1  = (const float*)d_in[4];
    const float* b1   = (const float*)d_in[5];
    const float* W2   = (const float*)d_in[6];
    const float* as2  = (const float*)d_in[7];
    const float* ad2  = (const float*)d_in[8];
    const float* b2   = (const float*)d_in[9];
    float* out = (float*)d_out;

    int N  = in_sizes[0] / 256;
    int E  = in_sizes[1] / 2;
    int ET = E + N;
    int nsplit = 65536 + 256 * 64;

    // launch idx: 0 split_all; 1 detect+zero; 2 count; 3 gemm1_tc (profiled slot)
    k_split_all<<<(nsplit + 255) / 256, 256>>>(W1, W2);
    k_detect<<<(N + 255) / 256, 256>>>((const int*)edge, E, N);
    k_count<<<(ET + 255) / 256, 256>>>(edge, E, N);
    k_gemm1_tc<<<dim3(2, (N + 127) / 128), 256>>>(x, N, as1, ad1);

    // CSR completion
    k_scan_fused<<<1, 1024>>>(N);
    k_scatter<<<(ET + 255) / 256, 256>>>(edge, E, N);

    // Layer 1
    int warpGrid = (N * 32 + 255) / 256;
    k_agg1<<<warpGrid, 256>>>(b1, N);

    // Layer 2
    k_gemm2_tc<<<(N + 127) / 128, 256>>>(N, as2, ad2);
    k_agg2<<<warpGrid, 256>>>(b2, out, N);
}

// round 15
// speedup vs baseline: 1.1485x; 1.1485x over previous
#include <cuda_runtime.h>
#include <cuda_bf16.h>
#include <cuda_fp16.h>
#include <cstdint>
#include <math.h>

// ---------------- static scratch (no allocs allowed) ----------------
#define NMAX 50176
#define EMAX 1700000

__device__ __half g_h1f[NMAX * 256];          // x @ W1 (fp16, for agg1 gather)
__device__ __nv_bfloat16 g_h1ah[NMAX * 256], g_h1al[NMAX * 256]; // layer1 out, bf16 split
__device__ __half g_h2f[NMAX * 40];           // fp16 for agg2 gather
__device__ float g_as1[NMAX * 4], g_ad1[NMAX * 4];
__device__ float g_as2[NMAX],     g_ad2[NMAX];
__device__ int   g_deg[NMAX], g_off[NMAX + 1], g_cur[NMAX];
__device__ int   g_csr[EMAX];
__device__ int   g_is64;
// bf16 split operands for tensor-core GEMMs
__device__ __nv_bfloat16 g_wh[256 * 256],  g_wl[256 * 256];
__device__ __nv_bfloat16 g_w2h[256 * 64],  g_w2l[256 * 64];   // W2 padded 40->64

// ---------------- PTX helpers ----------------
__device__ __forceinline__ unsigned smem_u32(const void* p) {
    return (unsigned)__cvta_generic_to_shared(p);
}
__device__ __forceinline__ void ldsm_x4(unsigned addr, unsigned& r0, unsigned& r1, unsigned& r2, unsigned& r3) {
    asm volatile("ldmatrix.sync.aligned.m8n8.x4.shared.b16 {%0,%1,%2,%3},[%4];"
                 : "=r"(r0), "=r"(r1), "=r"(r2), "=r"(r3) : "r"(addr));
}
__device__ __forceinline__ void ldsm_x4t(unsigned addr, unsigned& r0, unsigned& r1, unsigned& r2, unsigned& r3) {
    asm volatile("ldmatrix.sync.aligned.m8n8.x4.trans.shared.b16 {%0,%1,%2,%3},[%4];"
                 : "=r"(r0), "=r"(r1), "=r"(r2), "=r"(r3) : "r"(addr));
}
__device__ __forceinline__ void mma_bf16(float* c, unsigned a0, unsigned a1, unsigned a2, unsigned a3,
                                         unsigned b0, unsigned b1) {
    asm volatile("mma.sync.aligned.m16n8k16.row.col.f32.bf16.bf16.f32 "
                 "{%0,%1,%2,%3},{%4,%5,%6,%7},{%8,%9},{%0,%1,%2,%3};"
                 : "+f"(c[0]), "+f"(c[1]), "+f"(c[2]), "+f"(c[3])
                 : "r"(a0), "r"(a1), "r"(a2), "r"(a3), "r"(b0), "r"(b1));
}

// ---------------- combined bf16 split: W1 (65536) + W2 padded (256x64) ----------------
__global__ void k_split_all(const float* __restrict__ W1, const float* __restrict__ W2) {
    int i = blockIdx.x * blockDim.x + threadIdx.x;
    if (i < 65536) {
        float v = W1[i];
        __nv_bfloat16 h = __float2bfloat16(v);
        g_wh[i] = h;
        g_wl[i] = __float2bfloat16(v - __bfloat162float(h));
    } else if (i < 65536 + 256 * 64) {
        int j = i - 65536;
        int r = j >> 6, c = j & 63;
        float v = (c < 40) ? W2[r * 40 + c] : 0.f;
        __nv_bfloat16 h = __float2bfloat16(v);
        g_w2h[j] = h;
        g_w2l[j] = __float2bfloat16(v - __bfloat162float(h));
    }
}

// ---------------- edge dtype detection + zero deg/as2/ad2 (fused) ----------------
__global__ void k_detect(const int* __restrict__ e32, int E, int N) {
    int i = blockIdx.x * blockDim.x + threadIdx.x;
    if (i < N) {
        g_deg[i] = 0;
        g_as2[i] = 0.f;
        g_ad2[i] = 0.f;
    }
    if (blockIdx.x == 0 && threadIdx.x < 32) {
        int lane = threadIdx.x;
        int nz = 0;
        for (int k = lane; k < 64; k += 32)
            if (k < E) nz |= (e32[2 * k + 1] != 0);
        unsigned b = __ballot_sync(0xffffffffu, nz);
        if (lane == 0) g_is64 = (b == 0u);
    }
}

__device__ __forceinline__ int edge_at(const void* edge, int is64, long long idx) {
    if (is64) return (int)((const long long*)edge)[idx];
    return ((const int*)edge)[idx];
}

// ---------------- CSR build ----------------
__global__ void k_count(const void* __restrict__ edge, int E, int N) {
    int e = blockIdx.x * blockDim.x + threadIdx.x;
    int ET = E + N;
    if (e >= ET) return;
    int is64 = g_is64;
    int dst = (e < E) ? edge_at(edge, is64, (long long)E + e) : (e - E);
    atomicAdd(&g_deg[dst], 1);
}

// ---------------- coalesced tiled scan: one block, tiles of 1024, warp-shuffle scan ----------------
__global__ void __launch_bounds__(1024) k_scan_tiled(int N) {
    __shared__ int wsum[32];
    int t = threadIdx.x;
    int lane = t & 31, wid = t >> 5;
    int run = 0;
    for (int tile = 0; tile < N; tile += 1024) {
        int idx = tile + t;
        int v = (idx < N) ? g_deg[idx] : 0;
        int incl = v;
#pragma unroll
        for (int o = 1; o < 32; o <<= 1) {
            int u = __shfl_up_sync(0xffffffffu, incl, o);
            if (lane >= o) incl += u;
        }
        if (lane == 31) wsum[wid] = incl;
        __syncthreads();
        if (wid == 0) {
            int wincl = wsum[lane];
#pragma unroll
            for (int o = 1; o < 32; o <<= 1) {
                int u = __shfl_up_sync(0xffffffffu, wincl, o);
                if (lane >= o) wincl += u;
            }
            wsum[lane] = wincl;
        }
        __syncthreads();
        int woff = (wid > 0) ? wsum[wid - 1] : 0;
        int ex = run + woff + incl - v;
        if (idx < N) { g_off[idx] = ex; g_cur[idx] = ex; }
        int total = wsum[31];
        __syncthreads();
        run += total;
    }
    if (t == 0) g_off[N] = run;
}

__global__ void k_scatter(const void* __restrict__ edge, int E, int N) {
    int e = blockIdx.x * blockDim.x + threadIdx.x;
    int ET = E + N;
    if (e >= ET) return;
    int src, dst;
    if (e < E) {
        int is64 = g_is64;
        src = edge_at(edge, is64, e);
        dst = edge_at(edge, is64, (long long)E + e);
    } else {
        src = dst = e - E;
    }
    int pos = atomicAdd(&g_cur[dst], 1);
    g_csr[pos] = src;
}

// ---------------- GEMM1: x fp32 loaded directly, split in-kernel; fused attn1 ----------------
#define LDA 40
#define LDB1 136
__global__ void __launch_bounds__(256, 2) k_gemm1_tc(const float* __restrict__ X, int M,
        const float* __restrict__ att_s, const float* __restrict__ att_d) {
    __shared__ __nv_bfloat16 Ah[128 * LDA], Al[128 * LDA];
    __shared__ __nv_bfloat16 Bh[32 * LDB1], Bl[32 * LDB1];
    int tid = threadIdx.x;
    int warp = tid >> 5, lane = tid & 31;
    int wm = warp & 3, wn = warp >> 2;
    int row0 = blockIdx.y * 128, col0 = blockIdx.x * 128;

    float acc[2][8][4];
#pragma unroll
    for (int mi = 0; mi < 2; mi++)
#pragma unroll
        for (int ni = 0; ni < 8; ni++)
#pragma unroll
            for (int k = 0; k < 4; k++) acc[mi][ni][k] = 0.f;

    int lrow = lane & 15, lcb = lane >> 4;

    for (int kt = 0; kt < 256; kt += 32) {
#pragma unroll
        for (int i = 0; i < 2; i++) {
            int v = tid + i * 256;
            int r = v >> 2, cv = (v & 3) * 8;
            int gr = row0 + r;
            float4 f0 = make_float4(0.f, 0.f, 0.f, 0.f), f1 = f0;
            if (gr < M) {
                f0 = *(const float4*)&X[(size_t)gr * 256 + kt + cv];
                f1 = *(const float4*)&X[(size_t)gr * 256 + kt + cv + 4];
            }
            float fv[8] = {f0.x, f0.y, f0.z, f0.w, f1.x, f1.y, f1.z, f1.w};
            __nv_bfloat16 hb[8], lb[8];
#pragma unroll
            for (int k = 0; k < 8; k++) {
                hb[k] = __float2bfloat16(fv[k]);
                lb[k] = __float2bfloat16(fv[k] - __bfloat162float(hb[k]));
            }
            *(uint4*)&Ah[r * LDA + cv] = *(const uint4*)hb;
            *(uint4*)&Al[r * LDA + cv] = *(const uint4*)lb;
        }
#pragma unroll
        for (int i = 0; i < 2; i++) {
            int v = tid + i * 256;
            int r = v >> 4, cv = (v & 15) * 8;
            *(uint4*)&Bh[r * LDB1 + cv] = *(const uint4*)&g_wh[(size_t)(kt + r) * 256 + col0 + cv];
            *(uint4*)&Bl[r * LDB1 + cv] = *(const uint4*)&g_wl[(size_t)(kt + r) * 256 + col0 + cv];
        }
        __syncthreads();

#pragma unroll
        for (int ks = 0; ks < 32; ks += 16) {
            unsigned ah[2][4], al[2][4], bh[4][4], bl[4][4];
#pragma unroll
            for (int mi = 0; mi < 2; mi++) {
                unsigned ad = smem_u32(&Ah[(wm * 32 + mi * 16 + lrow) * LDA + ks + lcb * 8]);
                ldsm_x4(ad, ah[mi][0], ah[mi][1], ah[mi][2], ah[mi][3]);
                unsigned ad2 = smem_u32(&Al[(wm * 32 + mi * 16 + lrow) * LDA + ks + lcb * 8]);
                ldsm_x4(ad2, al[mi][0], al[mi][1], al[mi][2], al[mi][3]);
            }
#pragma unroll
            for (int nj = 0; nj < 4; nj++) {
                unsigned bd = smem_u32(&Bh[(ks + lrow) * LDB1 + wn * 64 + nj * 16 + lcb * 8]);
                ldsm_x4t(bd, bh[nj][0], bh[nj][1], bh[nj][2], bh[nj][3]);
                unsigned bd2 = smem_u32(&Bl[(ks + lrow) * LDB1 + wn * 64 + nj * 16 + lcb * 8]);
                ldsm_x4t(bd2, bl[nj][0], bl[nj][1], bl[nj][2], bl[nj][3]);
            }
#pragma unroll
            for (int mi = 0; mi < 2; mi++)
#pragma unroll
                for (int ni = 0; ni < 8; ni++) {
                    int nj = ni >> 1, s2 = (ni & 1) * 2;
                    mma_bf16(acc[mi][ni], ah[mi][0], ah[mi][1], ah[mi][2], ah[mi][3],
                             bh[nj][s2], bh[nj][s2 + 1]);
                    mma_bf16(acc[mi][ni], ah[mi][0], ah[mi][1], ah[mi][2], ah[mi][3],
                             bl[nj][s2], bl[nj][s2 + 1]);
                    mma_bf16(acc[mi][ni], al[mi][0], al[mi][1], al[mi][2], al[mi][3],
                             bh[nj][s2], bh[nj][s2 + 1]);
                }
        }
        __syncthreads();
    }

    int tr = lane >> 2, tc = (lane & 3) * 2;
    int head = blockIdx.x * 2 + wn;
#pragma unroll
    for (int mi = 0; mi < 2; mi++) {
        float ps0 = 0.f, pd0 = 0.f, ps1 = 0.f, pd1 = 0.f;
#pragma unroll
        for (int ni = 0; ni < 8; ni++) {
            int r = row0 + wm * 32 + mi * 16 + tr;
            int c = col0 + wn * 64 + ni * 8 + tc;
            if (r < M)
                *(__half2*)&g_h1f[(size_t)r * 256 + c] = __floats2half2_rn(acc[mi][ni][0], acc[mi][ni][1]);
            if (r + 8 < M)
                *(__half2*)&g_h1f[(size_t)(r + 8) * 256 + c] = __floats2half2_rn(acc[mi][ni][2], acc[mi][ni][3]);
            float s0 = __ldg(&att_s[c]), s1 = __ldg(&att_s[c + 1]);
            float d0 = __ldg(&att_d[c]), d1 = __ldg(&att_d[c + 1]);
            ps0 = fmaf(acc[mi][ni][0], s0, ps0); ps0 = fmaf(acc[mi][ni][1], s1, ps0);
            pd0 = fmaf(acc[mi][ni][0], d0, pd0); pd0 = fmaf(acc[mi][ni][1], d1, pd0);
            ps1 = fmaf(acc[mi][ni][2], s0, ps1); ps1 = fmaf(acc[mi][ni][3], s1, ps1);
            pd1 = fmaf(acc[mi][ni][2], d0, pd1); pd1 = fmaf(acc[mi][ni][3], d1, pd1);
        }
        ps0 += __shfl_xor_sync(0xffffffffu, ps0, 1); ps0 += __shfl_xor_sync(0xffffffffu, ps0, 2);
        pd0 += __shfl_xor_sync(0xffffffffu, pd0, 1); pd0 += __shfl_xor_sync(0xffffffffu, pd0, 2);
        ps1 += __shfl_xor_sync(0xffffffffu, ps1, 1); ps1 += __shfl_xor_sync(0xffffffffu, ps1, 2);
        pd1 += __shfl_xor_sync(0xffffffffu, pd1, 1); pd1 += __shfl_xor_sync(0xffffffffu, pd1, 2);
        if ((lane & 3) == 0) {
            int r0 = row0 + wm * 32 + mi * 16 + tr;
            if (r0 < M)     { g_as1[r0 * 4 + head] = ps0; g_ad1[r0 * 4 + head] = pd0; }
            if (r0 + 8 < M) { g_as1[(r0 + 8) * 4 + head] = ps1; g_ad1[(r0 + 8) * 4 + head] = pd1; }
        }
    }
}

// ---------------- GEMM2 (tensor core): h2 = h1a @ W2pad, fused attn2 ----------------
#define LDB 72
__global__ void __launch_bounds__(256) k_gemm2_tc(int M,
        const float* __restrict__ att_s, const float* __restrict__ att_d) {
    __shared__ __nv_bfloat16 Ah[128 * LDA], Al[128 * LDA];
    __shared__ __nv_bfloat16 Bh[32 * LDB],  Bl[32 * LDB];
    int tid = threadIdx.x;
    int warp = tid >> 5, lane = tid & 31;
    int wm = warp & 3, wn = warp >> 2;
    int row0 = blockIdx.x * 128;

    float acc[2][4][4];
#pragma unroll
    for (int mi = 0; mi < 2; mi++)
#pragma unroll
        for (int ni = 0; ni < 4; ni++)
#pragma unroll
            for (int k = 0; k < 4; k++) acc[mi][ni][k] = 0.f;

    int lrow = lane & 15, lcb = lane >> 4;

    for (int kt = 0; kt < 256; kt += 32) {
#pragma unroll
        for (int i = 0; i < 2; i++) {
            int v = tid + i * 256;
            int r = v >> 2, cv = (v & 3) * 8;
            int gr = row0 + r;
            uint4 vh, vl;
            if (gr < M) {
                vh = *(const uint4*)&g_h1ah[(size_t)gr * 256 + kt + cv];
                vl = *(const uint4*)&g_h1al[(size_t)gr * 256 + kt + cv];
            } else { vh = make_uint4(0,0,0,0); vl = vh; }
            *(uint4*)&Ah[r * LDA + cv] = vh;
            *(uint4*)&Al[r * LDA + cv] = vl;
        }
        {
            int r = tid >> 3, cv = (tid & 7) * 8;
            *(uint4*)&Bh[r * LDB + cv] = *(const uint4*)&g_w2h[(size_t)(kt + r) * 64 + cv];
            *(uint4*)&Bl[r * LDB + cv] = *(const uint4*)&g_w2l[(size_t)(kt + r) * 64 + cv];
        }
        __syncthreads();

#pragma unroll
        for (int ks = 0; ks < 32; ks += 16) {
            unsigned ah[2][4], al[2][4], bh[2][4], bl[2][4];
#pragma unroll
            for (int mi = 0; mi < 2; mi++) {
                unsigned ad = smem_u32(&Ah[(wm * 32 + mi * 16 + lrow) * LDA + ks + lcb * 8]);
                ldsm_x4(ad, ah[mi][0], ah[mi][1], ah[mi][2], ah[mi][3]);
                unsigned ad2 = smem_u32(&Al[(wm * 32 + mi * 16 + lrow) * LDA + ks + lcb * 8]);
                ldsm_x4(ad2, al[mi][0], al[mi][1], al[mi][2], al[mi][3]);
            }
#pragma unroll
            for (int nj = 0; nj < 2; nj++) {
                unsigned bd = smem_u32(&Bh[(ks + lrow) * LDB + wn * 32 + nj * 16 + lcb * 8]);
                ldsm_x4t(bd, bh[nj][0], bh[nj][1], bh[nj][2], bh[nj][3]);
                unsigned bd2 = smem_u32(&Bl[(ks + lrow) * LDB + wn * 32 + nj * 16 + lcb * 8]);
                ldsm_x4t(bd2, bl[nj][0], bl[nj][1], bl[nj][2], bl[nj][3]);
            }
#pragma unroll
            for (int mi = 0; mi < 2; mi++)
#pragma unroll
                for (int ni = 0; ni < 4; ni++) {
                    int nj = ni >> 1, s2 = (ni & 1) * 2;
                    mma_bf16(acc[mi][ni], ah[mi][0], ah[mi][1], ah[mi][2], ah[mi][3],
                             bh[nj][s2], bh[nj][s2 + 1]);
                    mma_bf16(acc[mi][ni], ah[mi][0], ah[mi][1], ah[mi][2], ah[mi][3],
                             bl[nj][s2], bl[nj][s2 + 1]);
                    mma_bf16(acc[mi][ni], al[mi][0], al[mi][1], al[mi][2], al[mi][3],
                             bh[nj][s2], bh[nj][s2 + 1]);
                }
        }
        __syncthreads();
    }

    int tr = lane >> 2, tc = (lane & 3) * 2;
#pragma unroll
    for (int mi = 0; mi < 2; mi++) {
        float ps0 = 0.f, pd0 = 0.f, ps1 = 0.f, pd1 = 0.f;
#pragma unroll
        for (int ni = 0; ni < 4; ni++) {
            int r = row0 + wm * 32 + mi * 16 + tr;
            int c = wn * 32 + ni * 8 + tc;
            if (c < 40) {
                if (r < M)
                    *(__half2*)&g_h2f[(size_t)r * 40 + c] = __floats2half2_rn(acc[mi][ni][0], acc[mi][ni][1]);
                if (r + 8 < M)
                    *(__half2*)&g_h2f[(size_t)(r + 8) * 40 + c] = __floats2half2_rn(acc[mi][ni][2], acc[mi][ni][3]);
                float s0 = __ldg(&att_s[c]), s1 = __ldg(&att_s[c + 1]);
                float d0 = __ldg(&att_d[c]), d1 = __ldg(&att_d[c + 1]);
                ps0 = fmaf(acc[mi][ni][0], s0, ps0); ps0 = fmaf(acc[mi][ni][1], s1, ps0);
                pd0 = fmaf(acc[mi][ni][0], d0, pd0); pd0 = fmaf(acc[mi][ni][1], d1, pd0);
                ps1 = fmaf(acc[mi][ni][2], s0, ps1); ps1 = fmaf(acc[mi][ni][3], s1, ps1);
                pd1 = fmaf(acc[mi][ni][2], d0, pd1); pd1 = fmaf(acc[mi][ni][3], d1, pd1);
            }
        }
        ps0 += __shfl_xor_sync(0xffffffffu, ps0, 1); ps0 += __shfl_xor_sync(0xffffffffu, ps0, 2);
        pd0 += __shfl_xor_sync(0xffffffffu, pd0, 1); pd0 += __shfl_xor_sync(0xffffffffu, pd0, 2);
        ps1 += __shfl_xor_sync(0xffffffffu, ps1, 1); ps1 += __shfl_xor_sync(0xffffffffu, ps1, 2);
        pd1 += __shfl_xor_sync(0xffffffffu, pd1, 1); pd1 += __shfl_xor_sync(0xffffffffu, pd1, 2);
        if ((lane & 3) == 0) {
            int r0 = row0 + wm * 32 + mi * 16 + tr;
            if (r0 < M)     { atomicAdd(&g_as2[r0], ps0); atomicAdd(&g_ad2[r0], pd0); }
            if (r0 + 8 < M) { atomicAdd(&g_as2[r0 + 8], ps1); atomicAdd(&g_ad2[r0 + 8], pd1); }
        }
    }
}

// ---------------- agg1: inline edge weights, fp16 gather, + bias + ELU, bf16-split out ----------------
__global__ void k_agg1(const float* __restrict__ bias, int M) {
    int w = (blockIdx.x * blockDim.x + threadIdx.x) >> 5;
    int lane = threadIdx.x & 31;
    if (w >= M) return;
    int start = g_off[w], end = g_off[w + 1];
    int hh = lane >> 3;
    int c0 = lane * 8;
    float4 adv = *(const float4*)&g_ad1[w * 4];
    float adh = (hh == 0) ? adv.x : (hh == 1) ? adv.y : (hh == 2) ? adv.z : adv.w;

    float acc[8] = {0.f, 0.f, 0.f, 0.f, 0.f, 0.f, 0.f, 0.f};
    float denom = 0.f;
    int j = start;
    for (; j + 1 < end; j += 2) {
        int s0 = g_csr[j], s1 = g_csr[j + 1];
        float e0 = g_as1[s0 * 4 + hh] + adh;
        float e1 = g_as1[s1 * 4 + hh] + adh;
        e0 = e0 > 0.f ? e0 : 0.2f * e0;
        e1 = e1 > 0.f ? e1 : 0.2f * e1;
        float w0 = __expf(e0), w1 = __expf(e1);
        uint4 q0 = *(const uint4*)&g_h1f[(size_t)s0 * 256 + c0];
        uint4 q1 = *(const uint4*)&g_h1f[(size_t)s1 * 256 + c0];
        denom += w0 + w1;
        const __half2* a = (const __half2*)&q0;
        const __half2* b = (const __half2*)&q1;
#pragma unroll
        for (int k = 0; k < 4; k++) {
            float2 fa = __half22float2(a[k]);
            float2 fb = __half22float2(b[k]);
            acc[2*k]   = fmaf(w0, fa.x, acc[2*k]);   acc[2*k]   = fmaf(w1, fb.x, acc[2*k]);
            acc[2*k+1] = fmaf(w0, fa.y, acc[2*k+1]); acc[2*k+1] = fmaf(w1, fb.y, acc[2*k+1]);
        }
    }
    if (j < end) {
        int s0 = g_csr[j];
        float e0 = g_as1[s0 * 4 + hh] + adh;
        e0 = e0 > 0.f ? e0 : 0.2f * e0;
        float w0 = __expf(e0);
        uint4 q0 = *(const uint4*)&g_h1f[(size_t)s0 * 256 + c0];
        denom += w0;
        const __half2* a = (const __half2*)&q0;
#pragma unroll
        for (int k = 0; k < 4; k++) {
            float2 fa = __half22float2(a[k]);
            acc[2*k]   = fmaf(w0, fa.x, acc[2*k]);
            acc[2*k+1] = fmaf(w0, fa.y, acc[2*k+1]);
        }
    }
    float inv = 1.f / denom;
    __nv_bfloat16 hi8[8], lo8[8];
#pragma unroll
    for (int k = 0; k < 8; k++) {
        float v = acc[k] * inv + bias[c0 + k];
        v = v > 0.f ? v : (__expf(v) - 1.f);   // ELU
        __nv_bfloat16 h = __float2bfloat16(v);
        hi8[k] = h;
        lo8[k] = __float2bfloat16(v - __bfloat162float(h));
    }
    *(uint4*)&g_h1ah[(size_t)w * 256 + c0] = *(const uint4*)hi8;
    *(uint4*)&g_h1al[(size_t)w * 256 + c0] = *(const uint4*)lo8;
}

// ---------------- agg2: inline edge weights, fp16 gather, final output ----------------
__global__ void k_agg2(const float* __restrict__ b2, float* __restrict__ out, int M) {
    int w = (blockIdx.x * blockDim.x + threadIdx.x) >> 5;
    int lane = threadIdx.x & 31;
    if (w >= M) return;
    int start = g_off[w], end = g_off[w + 1];
    float adv = g_ad2[w];
    bool val = lane < 20;
    float denom = 0.f, acc0 = 0.f, acc1 = 0.f;
    int j = start;
    for (; j + 1 < end; j += 2) {
        int s0 = g_csr[j], s1 = g_csr[j + 1];
        float e0 = g_as2[s0] + adv;
        float e1 = g_as2[s1] + adv;
        e0 = e0 > 0.f ? e0 : 0.2f * e0;
        e1 = e1 > 0.f ? e1 : 0.2f * e1;
        float w0 = __expf(e0), w1 = __expf(e1);
        float2 f0 = make_float2(0.f, 0.f), f1 = f0;
        if (val) {
            f0 = __half22float2(*(const __half2*)&g_h2f[(size_t)s0 * 40 + lane * 2]);
            f1 = __half22float2(*(const __half2*)&g_h2f[(size_t)s1 * 40 + lane * 2]);
        }
        denom += w0 + w1;
        acc0 = fmaf(w0, f0.x, acc0); acc0 = fmaf(w1, f1.x, acc0);
        acc1 = fmaf(w0, f0.y, acc1); acc1 = fmaf(w1, f1.y, acc1);
    }
    if (j < end) {
        int s0 = g_csr[j];
        float e0 = g_as2[s0] + adv;
        e0 = e0 > 0.f ? e0 : 0.2f * e0;
        float w0 = __expf(e0);
        float2 f0 = make_float2(0.f, 0.f);
        if (val) f0 = __half22float2(*(const __half2*)&g_h2f[(size_t)s0 * 40 + lane * 2]);
        denom += w0;
        acc0 = fmaf(w0, f0.x, acc0);
        acc1 = fmaf(w0, f0.y, acc1);
    }
    float inv = 1.f / denom;
    if (val) {
        out[(size_t)w * 40 + lane * 2]     = acc0 * inv + __ldg(&b2[lane * 2]);
        out[(size_t)w * 40 + lane * 2 + 1] = acc1 * inv + __ldg(&b2[lane * 2 + 1]);
    }
}

// ---------------- launch ----------------
extern "C" void kernel_launch(void* const* d_in, const int* in_sizes, int n_in,
                              void* d_out, int out_size) {
    const float* x    = (const float*)d_in[0];
    const void*  edge = (const void*)d_in[1];
    const float* W1   = (const float*)d_in[2];
    const float* as1  = (const float*)d_in[3];
    const float* ad1  = (const float*)d_in[4];
    const float* b1   = (const float*)d_in[5];
    const float* W2   = (const float*)d_in[6];
    const float* as2  = (const float*)d_in[7];
    const float* ad2  = (const float*)d_in[8];
    const float* b2   = (const float*)d_in[9];
    float* out = (float*)d_out;

    int N  = in_sizes[0] / 256;
    int E  = in_sizes[1] / 2;
    int ET = E + N;
    int nsplit = 65536 + 256 * 64;

    // launch idx: 0 split_all; 1 detect+zero; 2 count; 3 gemm1_tc (profiled slot)
    k_split_all<<<(nsplit + 255) / 256, 256>>>(W1, W2);
    k_detect<<<(N + 255) / 256, 256>>>((const int*)edge, E, N);
    k_count<<<(ET + 255) / 256, 256>>>(edge, E, N);
    k_gemm1_tc<<<dim3(2, (N + 127) / 128), 256>>>(x, N, as1, ad1);

    // CSR completion
    k_scan_tiled<<<1, 1024>>>(N);
    k_scatter<<<(ET + 255) / 256, 256>>>(edge, E, N);

    // Layer 1
    int warpGrid = (N * 32 + 255) / 256;
    k_agg1<<<warpGrid, 256>>>(b1, N);

    // Layer 2
    k_gemm2_tc<<<(N + 127) / 128, 256>>>(N, as2, ad2);
    k_agg2<<<warpGrid, 256>>>(b2, out, N);
}

// round 16
// speedup vs baseline: 1.1541x; 1.0049x over previous
#include <cuda_runtime.h>
#include <cuda_bf16.h>
#include <cuda_fp16.h>
#include <cstdint>
#include <math.h>

// ---------------- static scratch (no allocs allowed) ----------------
#define NMAX 50176
#define EMAX 1700000

__device__ __half g_h1f[NMAX * 256];          // x @ W1 (fp16, for agg1 gather)
__device__ __nv_bfloat16 g_h1ah[NMAX * 256], g_h1al[NMAX * 256]; // layer1 out, bf16 split
__device__ __half g_h2f[NMAX * 64];           // fp16 for agg2 gather (rows padded 40->64, 128B aligned)
__device__ float g_as1[NMAX * 4], g_ad1[NMAX * 4];
__device__ float g_as2[NMAX],     g_ad2[NMAX];
__device__ int   g_deg[NMAX], g_off[NMAX + 1], g_cur[NMAX];
__device__ int   g_csr[EMAX];
__device__ int   g_is64;
// bf16 split operands for tensor-core GEMMs
__device__ __nv_bfloat16 g_wh[256 * 256],  g_wl[256 * 256];
__device__ __nv_bfloat16 g_w2h[256 * 64],  g_w2l[256 * 64];   // W2 padded 40->64

// ---------------- PTX helpers ----------------
__device__ __forceinline__ unsigned smem_u32(const void* p) {
    return (unsigned)__cvta_generic_to_shared(p);
}
__device__ __forceinline__ void ldsm_x4(unsigned addr, unsigned& r0, unsigned& r1, unsigned& r2, unsigned& r3) {
    asm volatile("ldmatrix.sync.aligned.m8n8.x4.shared.b16 {%0,%1,%2,%3},[%4];"
                 : "=r"(r0), "=r"(r1), "=r"(r2), "=r"(r3) : "r"(addr));
}
__device__ __forceinline__ void ldsm_x4t(unsigned addr, unsigned& r0, unsigned& r1, unsigned& r2, unsigned& r3) {
    asm volatile("ldmatrix.sync.aligned.m8n8.x4.trans.shared.b16 {%0,%1,%2,%3},[%4];"
                 : "=r"(r0), "=r"(r1), "=r"(r2), "=r"(r3) : "r"(addr));
}
__device__ __forceinline__ void mma_bf16(float* c, unsigned a0, unsigned a1, unsigned a2, unsigned a3,
                                         unsigned b0, unsigned b1) {
    asm volatile("mma.sync.aligned.m16n8k16.row.col.f32.bf16.bf16.f32 "
                 "{%0,%1,%2,%3},{%4,%5,%6,%7},{%8,%9},{%0,%1,%2,%3};"
                 : "+f"(c[0]), "+f"(c[1]), "+f"(c[2]), "+f"(c[3])
                 : "r"(a0), "r"(a1), "r"(a2), "r"(a3), "r"(b0), "r"(b1));
}

// ---------------- combined: W1/W2 bf16 split + zero deg/as2/ad2 ----------------
__global__ void k_split_all(const float* __restrict__ W1, const float* __restrict__ W2, int N) {
    int i = blockIdx.x * blockDim.x + threadIdx.x;
    if (i < N) {
        g_deg[i] = 0;
        g_as2[i] = 0.f;
        g_ad2[i] = 0.f;
    }
    if (i < 65536) {
        float v = W1[i];
        __nv_bfloat16 h = __float2bfloat16(v);
        g_wh[i] = h;
        g_wl[i] = __float2bfloat16(v - __bfloat162float(h));
    } else if (i < 65536 + 256 * 64) {
        int j = i - 65536;
        int r = j >> 6, c = j & 63;
        float v = (c < 40) ? W2[r * 40 + c] : 0.f;
        __nv_bfloat16 h = __float2bfloat16(v);
        g_w2h[j] = h;
        g_w2l[j] = __float2bfloat16(v - __bfloat162float(h));
    }
}

// ---------------- edge dtype detection (1 warp) ----------------
__global__ void k_detect(const int* __restrict__ e32, int E) {
    int lane = threadIdx.x;
    int nz = 0;
    for (int k = lane; k < 64; k += 32)
        if (k < E) nz |= (e32[2 * k + 1] != 0);
    unsigned b = __ballot_sync(0xffffffffu, nz);
    if (lane == 0) g_is64 = (b == 0u);
}

__device__ __forceinline__ int edge_at(const void* edge, int is64, long long idx) {
    if (is64) return (int)((const long long*)edge)[idx];
    return ((const int*)edge)[idx];
}

// ---------------- CSR build ----------------
__global__ void k_count(const void* __restrict__ edge, int E, int N) {
    int e = blockIdx.x * blockDim.x + threadIdx.x;
    int ET = E + N;
    if (e >= ET) return;
    int is64 = g_is64;
    int dst = (e < E) ? edge_at(edge, is64, (long long)E + e) : (e - E);
    atomicAdd(&g_deg[dst], 1);
}

// ---------------- coalesced tiled scan: one block, tiles of 1024, warp-shuffle scan ----------------
__global__ void __launch_bounds__(1024) k_scan_tiled(int N) {
    __shared__ int wsum[32];
    int t = threadIdx.x;
    int lane = t & 31, wid = t >> 5;
    int run = 0;
    for (int tile = 0; tile < N; tile += 1024) {
        int idx = tile + t;
        int v = (idx < N) ? g_deg[idx] : 0;
        int incl = v;
#pragma unroll
        for (int o = 1; o < 32; o <<= 1) {
            int u = __shfl_up_sync(0xffffffffu, incl, o);
            if (lane >= o) incl += u;
        }
        if (lane == 31) wsum[wid] = incl;
        __syncthreads();
        if (wid == 0) {
            int wincl = wsum[lane];
#pragma unroll
            for (int o = 1; o < 32; o <<= 1) {
                int u = __shfl_up_sync(0xffffffffu, wincl, o);
                if (lane >= o) wincl += u;
            }
            wsum[lane] = wincl;
        }
        __syncthreads();
        int woff = (wid > 0) ? wsum[wid - 1] : 0;
        int ex = run + woff + incl - v;
        if (idx < N) { g_off[idx] = ex; g_cur[idx] = ex; }
        int total = wsum[31];
        __syncthreads();
        run += total;
    }
    if (t == 0) g_off[N] = run;
}

__global__ void k_scatter(const void* __restrict__ edge, int E, int N) {
    int e = blockIdx.x * blockDim.x + threadIdx.x;
    int ET = E + N;
    if (e >= ET) return;
    int src, dst;
    if (e < E) {
        int is64 = g_is64;
        src = edge_at(edge, is64, e);
        dst = edge_at(edge, is64, (long long)E + e);
    } else {
        src = dst = e - E;
    }
    int pos = atomicAdd(&g_cur[dst], 1);
    g_csr[pos] = src;
}

// ---------------- GEMM1: x fp32 loaded directly, split in-kernel; fused attn1 ----------------
#define LDA 40
#define LDB1 136
__global__ void __launch_bounds__(256, 2) k_gemm1_tc(const float* __restrict__ X, int M,
        const float* __restrict__ att_s, const float* __restrict__ att_d) {
    __shared__ __nv_bfloat16 Ah[128 * LDA], Al[128 * LDA];
    __shared__ __nv_bfloat16 Bh[32 * LDB1], Bl[32 * LDB1];
    int tid = threadIdx.x;
    int warp = tid >> 5, lane = tid & 31;
    int wm = warp & 3, wn = warp >> 2;
    int row0 = blockIdx.y * 128, col0 = blockIdx.x * 128;

    float acc[2][8][4];
#pragma unroll
    for (int mi = 0; mi < 2; mi++)
#pragma unroll
        for (int ni = 0; ni < 8; ni++)
#pragma unroll
            for (int k = 0; k < 4; k++) acc[mi][ni][k] = 0.f;

    int lrow = lane & 15, lcb = lane >> 4;

    for (int kt = 0; kt < 256; kt += 32) {
#pragma unroll
        for (int i = 0; i < 2; i++) {
            int v = tid + i * 256;
            int r = v >> 2, cv = (v & 3) * 8;
            int gr = row0 + r;
            float4 f0 = make_float4(0.f, 0.f, 0.f, 0.f), f1 = f0;
            if (gr < M) {
                f0 = *(const float4*)&X[(size_t)gr * 256 + kt + cv];
                f1 = *(const float4*)&X[(size_t)gr * 256 + kt + cv + 4];
            }
            float fv[8] = {f0.x, f0.y, f0.z, f0.w, f1.x, f1.y, f1.z, f1.w};
            __nv_bfloat16 hb[8], lb[8];
#pragma unroll
            for (int k = 0; k < 8; k++) {
                hb[k] = __float2bfloat16(fv[k]);
                lb[k] = __float2bfloat16(fv[k] - __bfloat162float(hb[k]));
            }
            *(uint4*)&Ah[r * LDA + cv] = *(const uint4*)hb;
            *(uint4*)&Al[r * LDA + cv] = *(const uint4*)lb;
        }
#pragma unroll
        for (int i = 0; i < 2; i++) {
            int v = tid + i * 256;
            int r = v >> 4, cv = (v & 15) * 8;
            *(uint4*)&Bh[r * LDB1 + cv] = *(const uint4*)&g_wh[(size_t)(kt + r) * 256 + col0 + cv];
            *(uint4*)&Bl[r * LDB1 + cv] = *(const uint4*)&g_wl[(size_t)(kt + r) * 256 + col0 + cv];
        }
        __syncthreads();

#pragma unroll
        for (int ks = 0; ks < 32; ks += 16) {
            unsigned ah[2][4], al[2][4], bh[4][4], bl[4][4];
#pragma unroll
            for (int mi = 0; mi < 2; mi++) {
                unsigned ad = smem_u32(&Ah[(wm * 32 + mi * 16 + lrow) * LDA + ks + lcb * 8]);
                ldsm_x4(ad, ah[mi][0], ah[mi][1], ah[mi][2], ah[mi][3]);
                unsigned ad2 = smem_u32(&Al[(wm * 32 + mi * 16 + lrow) * LDA + ks + lcb * 8]);
                ldsm_x4(ad2, al[mi][0], al[mi][1], al[mi][2], al[mi][3]);
            }
#pragma unroll
            for (int nj = 0; nj < 4; nj++) {
                unsigned bd = smem_u32(&Bh[(ks + lrow) * LDB1 + wn * 64 + nj * 16 + lcb * 8]);
                ldsm_x4t(bd, bh[nj][0], bh[nj][1], bh[nj][2], bh[nj][3]);
                unsigned bd2 = smem_u32(&Bl[(ks + lrow) * LDB1 + wn * 64 + nj * 16 + lcb * 8]);
                ldsm_x4t(bd2, bl[nj][0], bl[nj][1], bl[nj][2], bl[nj][3]);
            }
#pragma unroll
            for (int mi = 0; mi < 2; mi++)
#pragma unroll
                for (int ni = 0; ni < 8; ni++) {
                    int nj = ni >> 1, s2 = (ni & 1) * 2;
                    mma_bf16(acc[mi][ni], ah[mi][0], ah[mi][1], ah[mi][2], ah[mi][3],
                             bh[nj][s2], bh[nj][s2 + 1]);
                    mma_bf16(acc[mi][ni], ah[mi][0], ah[mi][1], ah[mi][2], ah[mi][3],
                             bl[nj][s2], bl[nj][s2 + 1]);
                    mma_bf16(acc[mi][ni], al[mi][0], al[mi][1], al[mi][2], al[mi][3],
                             bh[nj][s2], bh[nj][s2 + 1]);
                }
        }
        __syncthreads();
    }

    int tr = lane >> 2, tc = (lane & 3) * 2;
    int head = blockIdx.x * 2 + wn;
#pragma unroll
    for (int mi = 0; mi < 2; mi++) {
        float ps0 = 0.f, pd0 = 0.f, ps1 = 0.f, pd1 = 0.f;
#pragma unroll
        for (int ni = 0; ni < 8; ni++) {
            int r = row0 + wm * 32 + mi * 16 + tr;
            int c = col0 + wn * 64 + ni * 8 + tc;
            if (r < M)
                *(__half2*)&g_h1f[(size_t)r * 256 + c] = __floats2half2_rn(acc[mi][ni][0], acc[mi][ni][1]);
            if (r + 8 < M)
                *(__half2*)&g_h1f[(size_t)(r + 8) * 256 + c] = __floats2half2_rn(acc[mi][ni][2], acc[mi][ni][3]);
            float s0 = __ldg(&att_s[c]), s1 = __ldg(&att_s[c + 1]);
            float d0 = __ldg(&att_d[c]), d1 = __ldg(&att_d[c + 1]);
            ps0 = fmaf(acc[mi][ni][0], s0, ps0); ps0 = fmaf(acc[mi][ni][1], s1, ps0);
            pd0 = fmaf(acc[mi][ni][0], d0, pd0); pd0 = fmaf(acc[mi][ni][1], d1, pd0);
            ps1 = fmaf(acc[mi][ni][2], s0, ps1); ps1 = fmaf(acc[mi][ni][3], s1, ps1);
            pd1 = fmaf(acc[mi][ni][2], d0, pd1); pd1 = fmaf(acc[mi][ni][3], d1, pd1);
        }
        ps0 += __shfl_xor_sync(0xffffffffu, ps0, 1); ps0 += __shfl_xor_sync(0xffffffffu, ps0, 2);
        pd0 += __shfl_xor_sync(0xffffffffu, pd0, 1); pd0 += __shfl_xor_sync(0xffffffffu, pd0, 2);
        ps1 += __shfl_xor_sync(0xffffffffu, ps1, 1); ps1 += __shfl_xor_sync(0xffffffffu, ps1, 2);
        pd1 += __shfl_xor_sync(0xffffffffu, pd1, 1); pd1 += __shfl_xor_sync(0xffffffffu, pd1, 2);
        if ((lane & 3) == 0) {
            int r0 = row0 + wm * 32 + mi * 16 + tr;
            if (r0 < M)     { g_as1[r0 * 4 + head] = ps0; g_ad1[r0 * 4 + head] = pd0; }
            if (r0 + 8 < M) { g_as1[(r0 + 8) * 4 + head] = ps1; g_ad1[(r0 + 8) * 4 + head] = pd1; }
        }
    }
}

// ---------------- GEMM2 (tensor core): h2 = h1a @ W2pad, fused attn2 ----------------
#define LDB 72
__global__ void __launch_bounds__(256) k_gemm2_tc(int M,
        const float* __restrict__ att_s, const float* __restrict__ att_d) {
    __shared__ __nv_bfloat16 Ah[128 * LDA], Al[128 * LDA];
    __shared__ __nv_bfloat16 Bh[32 * LDB],  Bl[32 * LDB];
    int tid = threadIdx.x;
    int warp = tid >> 5, lane = tid & 31;
    int wm = warp & 3, wn = warp >> 2;
    int row0 = blockIdx.x * 128;

    float acc[2][4][4];
#pragma unroll
    for (int mi = 0; mi < 2; mi++)
#pragma unroll
        for (int ni = 0; ni < 4; ni++)
#pragma unroll
            for (int k = 0; k < 4; k++) acc[mi][ni][k] = 0.f;

    int lrow = lane & 15, lcb = lane >> 4;

    for (int kt = 0; kt < 256; kt += 32) {
#pragma unroll
        for (int i = 0; i < 2; i++) {
            int v = tid + i * 256;
            int r = v >> 2, cv = (v & 3) * 8;
            int gr = row0 + r;
            uint4 vh, vl;
            if (gr < M) {
                vh = *(const uint4*)&g_h1ah[(size_t)gr * 256 + kt + cv];
                vl = *(const uint4*)&g_h1al[(size_t)gr * 256 + kt + cv];
            } else { vh = make_uint4(0,0,0,0); vl = vh; }
            *(uint4*)&Ah[r * LDA + cv] = vh;
            *(uint4*)&Al[r * LDA + cv] = vl;
        }
        {
            int r = tid >> 3, cv = (tid & 7) * 8;
            *(uint4*)&Bh[r * LDB + cv] = *(const uint4*)&g_w2h[(size_t)(kt + r) * 64 + cv];
            *(uint4*)&Bl[r * LDB + cv] = *(const uint4*)&g_w2l[(size_t)(kt + r) * 64 + cv];
        }
        __syncthreads();

#pragma unroll
        for (int ks = 0; ks < 32; ks += 16) {
            unsigned ah[2][4], al[2][4], bh[2][4], bl[2][4];
#pragma unroll
            for (int mi = 0; mi < 2; mi++) {
                unsigned ad = smem_u32(&Ah[(wm * 32 + mi * 16 + lrow) * LDA + ks + lcb * 8]);
                ldsm_x4(ad, ah[mi][0], ah[mi][1], ah[mi][2], ah[mi][3]);
                unsigned ad2 = smem_u32(&Al[(wm * 32 + mi * 16 + lrow) * LDA + ks + lcb * 8]);
                ldsm_x4(ad2, al[mi][0], al[mi][1], al[mi][2], al[mi][3]);
            }
#pragma unroll
            for (int nj = 0; nj < 2; nj++) {
                unsigned bd = smem_u32(&Bh[(ks + lrow) * LDB + wn * 32 + nj * 16 + lcb * 8]);
                ldsm_x4t(bd, bh[nj][0], bh[nj][1], bh[nj][2], bh[nj][3]);
                unsigned bd2 = smem_u32(&Bl[(ks + lrow) * LDB + wn * 32 + nj * 16 + lcb * 8]);
                ldsm_x4t(bd2, bl[nj][0], bl[nj][1], bl[nj][2], bl[nj][3]);
            }
#pragma unroll
            for (int mi = 0; mi < 2; mi++)
#pragma unroll
                for (int ni = 0; ni < 4; ni++) {
                    int nj = ni >> 1, s2 = (ni & 1) * 2;
                    mma_bf16(acc[mi][ni], ah[mi][0], ah[mi][1], ah[mi][2], ah[mi][3],
                             bh[nj][s2], bh[nj][s2 + 1]);
                    mma_bf16(acc[mi][ni], ah[mi][0], ah[mi][1], ah[mi][2], ah[mi][3],
                             bl[nj][s2], bl[nj][s2 + 1]);
                    mma_bf16(acc[mi][ni], al[mi][0], al[mi][1], al[mi][2], al[mi][3],
                             bh[nj][s2], bh[nj][s2 + 1]);
                }
        }
        __syncthreads();
    }

    int tr = lane >> 2, tc = (lane & 3) * 2;
#pragma unroll
    for (int mi = 0; mi < 2; mi++) {
        float ps0 = 0.f, pd0 = 0.f, ps1 = 0.f, pd1 = 0.f;
#pragma unroll
        for (int ni = 0; ni < 4; ni++) {
            int r = row0 + wm * 32 + mi * 16 + tr;
            int c = wn * 32 + ni * 8 + tc;
            if (c < 40) {
                if (r < M)
                    *(__half2*)&g_h2f[(size_t)r * 64 + c] = __floats2half2_rn(acc[mi][ni][0], acc[mi][ni][1]);
                if (r + 8 < M)
                    *(__half2*)&g_h2f[(size_t)(r + 8) * 64 + c] = __floats2half2_rn(acc[mi][ni][2], acc[mi][ni][3]);
                float s0 = __ldg(&att_s[c]), s1 = __ldg(&att_s[c + 1]);
                float d0 = __ldg(&att_d[c]), d1 = __ldg(&att_d[c + 1]);
                ps0 = fmaf(acc[mi][ni][0], s0, ps0); ps0 = fmaf(acc[mi][ni][1], s1, ps0);
                pd0 = fmaf(acc[mi][ni][0], d0, pd0); pd0 = fmaf(acc[mi][ni][1], d1, pd0);
                ps1 = fmaf(acc[mi][ni][2], s0, ps1); ps1 = fmaf(acc[mi][ni][3], s1, ps1);
                pd1 = fmaf(acc[mi][ni][2], d0, pd1); pd1 = fmaf(acc[mi][ni][3], d1, pd1);
            }
        }
        ps0 += __shfl_xor_sync(0xffffffffu, ps0, 1); ps0 += __shfl_xor_sync(0xffffffffu, ps0, 2);
        pd0 += __shfl_xor_sync(0xffffffffu, pd0, 1); pd0 += __shfl_xor_sync(0xffffffffu, pd0, 2);
        ps1 += __shfl_xor_sync(0xffffffffu, ps1, 1); ps1 += __shfl_xor_sync(0xffffffffu, ps1, 2);
        pd1 += __shfl_xor_sync(0xffffffffu, pd1, 1); pd1 += __shfl_xor_sync(0xffffffffu, pd1, 2);
        if ((lane & 3) == 0) {
            int r0 = row0 + wm * 32 + mi * 16 + tr;
            if (r0 < M)     { atomicAdd(&g_as2[r0], ps0); atomicAdd(&g_ad2[r0], pd0); }
            if (r0 + 8 < M) { atomicAdd(&g_as2[r0 + 8], ps1); atomicAdd(&g_ad2[r0 + 8], pd1); }
        }
    }
}

// ---------------- agg1: inline edge weights, fp16 gather, + bias + ELU, bf16-split out ----------------
__global__ void k_agg1(const float* __restrict__ bias, int M) {
    int w = (blockIdx.x * blockDim.x + threadIdx.x) >> 5;
    int lane = threadIdx.x & 31;
    if (w >= M) return;
    int start = g_off[w], end = g_off[w + 1];
    int hh = lane >> 3;
    int c0 = lane * 8;
    float4 adv = *(const float4*)&g_ad1[w * 4];
    float adh = (hh == 0) ? adv.x : (hh == 1) ? adv.y : (hh == 2) ? adv.z : adv.w;

    float acc[8] = {0.f, 0.f, 0.f, 0.f, 0.f, 0.f, 0.f, 0.f};
    float denom = 0.f;
    int j = start;
    for (; j + 1 < end; j += 2) {
        int s0 = g_csr[j], s1 = g_csr[j + 1];
        float e0 = g_as1[s0 * 4 + hh] + adh;
        float e1 = g_as1[s1 * 4 + hh] + adh;
        e0 = e0 > 0.f ? e0 : 0.2f * e0;
        e1 = e1 > 0.f ? e1 : 0.2f * e1;
        float w0 = __expf(e0), w1 = __expf(e1);
        uint4 q0 = *(const uint4*)&g_h1f[(size_t)s0 * 256 + c0];
        uint4 q1 = *(const uint4*)&g_h1f[(size_t)s1 * 256 + c0];
        denom += w0 + w1;
        const __half2* a = (const __half2*)&q0;
        const __half2* b = (const __half2*)&q1;
#pragma unroll
        for (int k = 0; k < 4; k++) {
            float2 fa = __half22float2(a[k]);
            float2 fb = __half22float2(b[k]);
            acc[2*k]   = fmaf(w0, fa.x, acc[2*k]);   acc[2*k]   = fmaf(w1, fb.x, acc[2*k]);
            acc[2*k+1] = fmaf(w0, fa.y, acc[2*k+1]); acc[2*k+1] = fmaf(w1, fb.y, acc[2*k+1]);
        }
    }
    if (j < end) {
        int s0 = g_csr[j];
        float e0 = g_as1[s0 * 4 + hh] + adh;
        e0 = e0 > 0.f ? e0 : 0.2f * e0;
        float w0 = __expf(e0);
        uint4 q0 = *(const uint4*)&g_h1f[(size_t)s0 * 256 + c0];
        denom += w0;
        const __half2* a = (const __half2*)&q0;
#pragma unroll
        for (int k = 0; k < 4; k++) {
            float2 fa = __half22float2(a[k]);
            acc[2*k]   = fmaf(w0, fa.x, acc[2*k]);
            acc[2*k+1] = fmaf(w0, fa.y, acc[2*k+1]);
        }
    }
    float inv = 1.f / denom;
    __nv_bfloat16 hi8[8], lo8[8];
#pragma unroll
    for (int k = 0; k < 8; k++) {
        float v = acc[k] * inv + bias[c0 + k];
        v = v > 0.f ? v : (__expf(v) - 1.f);   // ELU
        __nv_bfloat16 h = __float2bfloat16(v);
        hi8[k] = h;
        lo8[k] = __float2bfloat16(v - __bfloat162float(h));
    }
    *(uint4*)&g_h1ah[(size_t)w * 256 + c0] = *(const uint4*)hi8;
    *(uint4*)&g_h1al[(size_t)w * 256 + c0] = *(const uint4*)lo8;
}

// ---------------- agg2: inline edge weights, padded fp16 gather, final output ----------------
__global__ void k_agg2(const float* __restrict__ b2, float* __restrict__ out, int M) {
    int w = (blockIdx.x * blockDim.x + threadIdx.x) >> 5;
    int lane = threadIdx.x & 31;
    if (w >= M) return;
    int start = g_off[w], end = g_off[w + 1];
    float adv = g_ad2[w];
    bool val = lane < 20;
    float denom = 0.f, acc0 = 0.f, acc1 = 0.f;
    int j = start;
    for (; j + 1 < end; j += 2) {
        int s0 = g_csr[j], s1 = g_csr[j + 1];
        float e0 = g_as2[s0] + adv;
        float e1 = g_as2[s1] + adv;
        e0 = e0 > 0.f ? e0 : 0.2f * e0;
        e1 = e1 > 0.f ? e1 : 0.2f * e1;
        float w0 = __expf(e0), w1 = __expf(e1);
        float2 f0 = make_float2(0.f, 0.f), f1 = f0;
        if (val) {
            f0 = __half22float2(*(const __half2*)&g_h2f[(size_t)s0 * 64 + lane * 2]);
            f1 = __half22float2(*(const __half2*)&g_h2f[(size_t)s1 * 64 + lane * 2]);
        }
        denom += w0 + w1;
        acc0 = fmaf(w0, f0.x, acc0); acc0 = fmaf(w1, f1.x, acc0);
        acc1 = fmaf(w0, f0.y, acc1); acc1 = fmaf(w1, f1.y, acc1);
    }
    if (j < end) {
        int s0 = g_csr[j];
        float e0 = g_as2[s0] + adv;
        e0 = e0 > 0.f ? e0 : 0.2f * e0;
        float w0 = __expf(e0);
        float2 f0 = make_float2(0.f, 0.f);
        if (val) f0 = __half22float2(*(const __half2*)&g_h2f[(size_t)s0 * 64 + lane * 2]);
        denom += w0;
        acc0 = fmaf(w0, f0.x, acc0);
        acc1 = fmaf(w0, f0.y, acc1);
    }
    float inv = 1.f / denom;
    if (val) {
        out[(size_t)w * 40 + lane * 2]     = acc0 * inv + __ldg(&b2[lane * 2]);
        out[(size_t)w * 40 + lane * 2 + 1] = acc1 * inv + __ldg(&b2[lane * 2 + 1]);
    }
}

// ---------------- launch ----------------
extern "C" void kernel_launch(void* const* d_in, const int* in_sizes, int n_in,
                              void* d_out, int out_size) {
    const float* x    = (const float*)d_in[0];
    const void*  edge = (const void*)d_in[1];
    const float* W1   = (const float*)d_in[2];
    const float* as1  = (const float*)d_in[3];
    const float* ad1  = (const float*)d_in[4];
    const float* b1   = (const float*)d_in[5];
    const float* W2   = (const float*)d_in[6];
    const float* as2  = (const float*)d_in[7];
    const float* ad2  = (const float*)d_in[8];
    const float* b2   = (const float*)d_in[9];
    float* out = (float*)d_out;

    int N  = in_sizes[0] / 256;
    int E  = in_sizes[1] / 2;
    int ET = E + N;
    int nsplit = 65536 + 256 * 64;   // > NMAX, also covers the zeroing

    // launch idx: 0 split_all+zero; 1 detect; 2 count; 3 gemm1_tc (profiled slot)
    k_split_all<<<(nsplit + 255) / 256, 256>>>(W1, W2, N);
    k_detect<<<1, 32>>>((const int*)edge, E);
    k_count<<<(ET + 255) / 256, 256>>>(edge, E, N);
    k_gemm1_tc<<<dim3(2, (N + 127) / 128), 256>>>(x, N, as1, ad1);

    // CSR completion
    k_scan_tiled<<<1, 1024>>>(N);
    k_scatter<<<(ET + 255) / 256, 256>>>(edge, E, N);

    // Layer 1
    int warpGrid = (N * 32 + 255) / 256;
    k_agg1<<<warpGrid, 256>>>(b1, N);

    // Layer 2
    k_gemm2_tc<<<(N + 127) / 128, 256>>>(N, as2, ad2);
    k_agg2<<<warpGrid, 256>>>(b2, out, N);
}

// round 17
// speedup vs baseline: 1.1877x; 1.0291x over previous
#include <cuda_runtime.h>
#include <cuda_bf16.h>
#include <cuda_fp16.h>
#include <cstdint>
#include <math.h>

// ---------------- static scratch (no allocs allowed) ----------------
#define NMAX 50176
#define EMAX 1700000

__device__ __half g_h1f[NMAX * 256];          // x @ W1 (fp16, for agg1 gather)
__device__ __nv_bfloat16 g_h1ah[NMAX * 256], g_h1al[NMAX * 256]; // layer1 out, bf16 split
__device__ __half g_h2f[NMAX * 64];           // fp16 for agg2 gather (rows padded 40->64)
__device__ float g_as1[NMAX * 4], g_ad1[NMAX * 4];
__device__ float g_as2[NMAX],     g_ad2[NMAX];
__device__ int   g_deg[NMAX], g_off[NMAX + 1], g_cur[NMAX];
__device__ int   g_csr[EMAX];
__device__ int   g_is64;
// bf16 split operands for tensor-core GEMMs
__device__ __nv_bfloat16 g_wh[256 * 256],  g_wl[256 * 256];
__device__ __nv_bfloat16 g_w2h[256 * 64],  g_w2l[256 * 64];   // W2 padded 40->64

// ---------------- PTX helpers ----------------
__device__ __forceinline__ unsigned smem_u32(const void* p) {
    return (unsigned)__cvta_generic_to_shared(p);
}
__device__ __forceinline__ void ldsm_x4(unsigned addr, unsigned& r0, unsigned& r1, unsigned& r2, unsigned& r3) {
    asm volatile("ldmatrix.sync.aligned.m8n8.x4.shared.b16 {%0,%1,%2,%3},[%4];"
                 : "=r"(r0), "=r"(r1), "=r"(r2), "=r"(r3) : "r"(addr));
}
__device__ __forceinline__ void ldsm_x4t(unsigned addr, unsigned& r0, unsigned& r1, unsigned& r2, unsigned& r3) {
    asm volatile("ldmatrix.sync.aligned.m8n8.x4.trans.shared.b16 {%0,%1,%2,%3},[%4];"
                 : "=r"(r0), "=r"(r1), "=r"(r2), "=r"(r3) : "r"(addr));
}
__device__ __forceinline__ void mma_bf16(float* c, unsigned a0, unsigned a1, unsigned a2, unsigned a3,
                                         unsigned b0, unsigned b1) {
    asm volatile("mma.sync.aligned.m16n8k16.row.col.f32.bf16.bf16.f32 "
                 "{%0,%1,%2,%3},{%4,%5,%6,%7},{%8,%9},{%0,%1,%2,%3};"
                 : "+f"(c[0]), "+f"(c[1]), "+f"(c[2]), "+f"(c[3])
                 : "r"(a0), "r"(a1), "r"(a2), "r"(a3), "r"(b0), "r"(b1));
}

__device__ __forceinline__ int edge_at(const void* edge, int is64, long long idx) {
    if (is64) return (int)((const long long*)edge)[idx];
    return ((const int*)edge)[idx];
}

// ---------------- detect + zero (N-grid, 1-warp probe) ----------------
__global__ void k_detect(const int* __restrict__ e32, int E, int N) {
    int i = blockIdx.x * blockDim.x + threadIdx.x;
    if (i < N) {
        g_deg[i] = 0;
        g_as2[i] = 0.f;
        g_ad2[i] = 0.f;
    }
    if (blockIdx.x == 0 && threadIdx.x < 32) {
        int lane = threadIdx.x;
        int nz = 0;
        for (int k = lane; k < 64; k += 32)
            if (k < E) nz |= (e32[2 * k + 1] != 0);
        unsigned b = __ballot_sync(0xffffffffu, nz);
        if (lane == 0) g_is64 = (b == 0u);
    }
}

// ---------------- fused: W1/W2 bf16 split (blocks < SPLITB) + edge count (blocks >= SPLITB) ----------------
#define SPLITB 320
__global__ void k_split_count(const float* __restrict__ W1, const float* __restrict__ W2,
                              const void* __restrict__ edge, int E, int N) {
    if (blockIdx.x < SPLITB) {
        int i = blockIdx.x * blockDim.x + threadIdx.x;
        if (i < 65536) {
            float v = W1[i];
            __nv_bfloat16 h = __float2bfloat16(v);
            g_wh[i] = h;
            g_wl[i] = __float2bfloat16(v - __bfloat162float(h));
        } else if (i < 65536 + 256 * 64) {
            int j = i - 65536;
            int r = j >> 6, c = j & 63;
            float v = (c < 40) ? W2[r * 40 + c] : 0.f;
            __nv_bfloat16 h = __float2bfloat16(v);
            g_w2h[j] = h;
            g_w2l[j] = __float2bfloat16(v - __bfloat162float(h));
        }
    } else {
        int e = (blockIdx.x - SPLITB) * blockDim.x + threadIdx.x;
        int ET = E + N;
        if (e >= ET) return;
        int is64 = g_is64;
        int dst = (e < E) ? edge_at(edge, is64, (long long)E + e) : (e - E);
        atomicAdd(&g_deg[dst], 1);
    }
}

// ---------------- coalesced tiled scan ----------------
__global__ void __launch_bounds__(1024) k_scan_tiled(int N) {
    __shared__ int wsum[32];
    int t = threadIdx.x;
    int lane = t & 31, wid = t >> 5;
    int run = 0;
    for (int tile = 0; tile < N; tile += 1024) {
        int idx = tile + t;
        int v = (idx < N) ? g_deg[idx] : 0;
        int incl = v;
#pragma unroll
        for (int o = 1; o < 32; o <<= 1) {
            int u = __shfl_up_sync(0xffffffffu, incl, o);
            if (lane >= o) incl += u;
        }
        if (lane == 31) wsum[wid] = incl;
        __syncthreads();
        if (wid == 0) {
            int wincl = wsum[lane];
#pragma unroll
            for (int o = 1; o < 32; o <<= 1) {
                int u = __shfl_up_sync(0xffffffffu, wincl, o);
                if (lane >= o) wincl += u;
            }
            wsum[lane] = wincl;
        }
        __syncthreads();
        int woff = (wid > 0) ? wsum[wid - 1] : 0;
        int ex = run + woff + incl - v;
        if (idx < N) { g_off[idx] = ex; g_cur[idx] = ex; }
        int total = wsum[31];
        __syncthreads();
        run += total;
    }
    if (t == 0) g_off[N] = run;
}

// ---------------- GEMM1 + fused attn1 + appended scatter blocks ----------------
#define LDA 40
#define LDB1 136
__global__ void __launch_bounds__(256, 2) k_gemm1_tc(const float* __restrict__ X, int M,
        const float* __restrict__ att_s, const float* __restrict__ att_d,
        const void* __restrict__ edge, int E, int rowBlocks) {
    // appended scatter blocks (whole-block branch; no __syncthreads on this path)
    if (blockIdx.y >= rowBlocks) {
        int ET = E + M;
        int e = ((blockIdx.y - rowBlocks) * 2 + blockIdx.x) * 256 + threadIdx.x;
        if (e < ET) {
            int src, dst;
            if (e < E) {
                int is64 = g_is64;
                src = edge_at(edge, is64, e);
                dst = edge_at(edge, is64, (long long)E + e);
            } else {
                src = dst = e - E;
            }
            int pos = atomicAdd(&g_cur[dst], 1);
            g_csr[pos] = src;
        }
        return;
    }

    __shared__ __nv_bfloat16 Ah[128 * LDA], Al[128 * LDA];
    __shared__ __nv_bfloat16 Bh[32 * LDB1], Bl[32 * LDB1];
    int tid = threadIdx.x;
    int warp = tid >> 5, lane = tid & 31;
    int wm = warp & 3, wn = warp >> 2;
    int row0 = blockIdx.y * 128, col0 = blockIdx.x * 128;

    float acc[2][8][4];
#pragma unroll
    for (int mi = 0; mi < 2; mi++)
#pragma unroll
        for (int ni = 0; ni < 8; ni++)
#pragma unroll
            for (int k = 0; k < 4; k++) acc[mi][ni][k] = 0.f;

    int lrow = lane & 15, lcb = lane >> 4;

    for (int kt = 0; kt < 256; kt += 32) {
#pragma unroll
        for (int i = 0; i < 2; i++) {
            int v = tid + i * 256;
            int r = v >> 2, cv = (v & 3) * 8;
            int gr = row0 + r;
            float4 f0 = make_float4(0.f, 0.f, 0.f, 0.f), f1 = f0;
            if (gr < M) {
                f0 = *(const float4*)&X[(size_t)gr * 256 + kt + cv];
                f1 = *(const float4*)&X[(size_t)gr * 256 + kt + cv + 4];
            }
            float fv[8] = {f0.x, f0.y, f0.z, f0.w, f1.x, f1.y, f1.z, f1.w};
            __nv_bfloat16 hb[8], lb[8];
#pragma unroll
            for (int k = 0; k < 8; k++) {
                hb[k] = __float2bfloat16(fv[k]);
                lb[k] = __float2bfloat16(fv[k] - __bfloat162float(hb[k]));
            }
            *(uint4*)&Ah[r * LDA + cv] = *(const uint4*)hb;
            *(uint4*)&Al[r * LDA + cv] = *(const uint4*)lb;
        }
#pragma unroll
        for (int i = 0; i < 2; i++) {
            int v = tid + i * 256;
            int r = v >> 4, cv = (v & 15) * 8;
            *(uint4*)&Bh[r * LDB1 + cv] = *(const uint4*)&g_wh[(size_t)(kt + r) * 256 + col0 + cv];
            *(uint4*)&Bl[r * LDB1 + cv] = *(const uint4*)&g_wl[(size_t)(kt + r) * 256 + col0 + cv];
        }
        __syncthreads();

#pragma unroll
        for (int ks = 0; ks < 32; ks += 16) {
            unsigned ah[2][4], al[2][4], bh[4][4], bl[4][4];
#pragma unroll
            for (int mi = 0; mi < 2; mi++) {
                unsigned ad = smem_u32(&Ah[(wm * 32 + mi * 16 + lrow) * LDA + ks + lcb * 8]);
                ldsm_x4(ad, ah[mi][0], ah[mi][1], ah[mi][2], ah[mi][3]);
                unsigned ad2 = smem_u32(&Al[(wm * 32 + mi * 16 + lrow) * LDA + ks + lcb * 8]);
                ldsm_x4(ad2, al[mi][0], al[mi][1], al[mi][2], al[mi][3]);
            }
#pragma unroll
            for (int nj = 0; nj < 4; nj++) {
                unsigned bd = smem_u32(&Bh[(ks + lrow) * LDB1 + wn * 64 + nj * 16 + lcb * 8]);
                ldsm_x4t(bd, bh[nj][0], bh[nj][1], bh[nj][2], bh[nj][3]);
                unsigned bd2 = smem_u32(&Bl[(ks + lrow) * LDB1 + wn * 64 + nj * 16 + lcb * 8]);
                ldsm_x4t(bd2, bl[nj][0], bl[nj][1], bl[nj][2], bl[nj][3]);
            }
#pragma unroll
            for (int mi = 0; mi < 2; mi++)
#pragma unroll
                for (int ni = 0; ni < 8; ni++) {
                    int nj = ni >> 1, s2 = (ni & 1) * 2;
                    mma_bf16(acc[mi][ni], ah[mi][0], ah[mi][1], ah[mi][2], ah[mi][3],
                             bh[nj][s2], bh[nj][s2 + 1]);
                    mma_bf16(acc[mi][ni], ah[mi][0], ah[mi][1], ah[mi][2], ah[mi][3],
                             bl[nj][s2], bl[nj][s2 + 1]);
                    mma_bf16(acc[mi][ni], al[mi][0], al[mi][1], al[mi][2], al[mi][3],
                             bh[nj][s2], bh[nj][s2 + 1]);
                }
        }
        __syncthreads();
    }

    int tr = lane >> 2, tc = (lane & 3) * 2;
    int head = blockIdx.x * 2 + wn;
#pragma unroll
    for (int mi = 0; mi < 2; mi++) {
        float ps0 = 0.f, pd0 = 0.f, ps1 = 0.f, pd1 = 0.f;
#pragma unroll
        for (int ni = 0; ni < 8; ni++) {
            int r = row0 + wm * 32 + mi * 16 + tr;
            int c = col0 + wn * 64 + ni * 8 + tc;
            if (r < M)
                *(__half2*)&g_h1f[(size_t)r * 256 + c] = __floats2half2_rn(acc[mi][ni][0], acc[mi][ni][1]);
            if (r + 8 < M)
                *(__half2*)&g_h1f[(size_t)(r + 8) * 256 + c] = __floats2half2_rn(acc[mi][ni][2], acc[mi][ni][3]);
            float s0 = __ldg(&att_s[c]), s1 = __ldg(&att_s[c + 1]);
            float d0 = __ldg(&att_d[c]), d1 = __ldg(&att_d[c + 1]);
            ps0 = fmaf(acc[mi][ni][0], s0, ps0); ps0 = fmaf(acc[mi][ni][1], s1, ps0);
            pd0 = fmaf(acc[mi][ni][0], d0, pd0); pd0 = fmaf(acc[mi][ni][1], d1, pd0);
            ps1 = fmaf(acc[mi][ni][2], s0, ps1); ps1 = fmaf(acc[mi][ni][3], s1, ps1);
            pd1 = fmaf(acc[mi][ni][2], d0, pd1); pd1 = fmaf(acc[mi][ni][3], d1, pd1);
        }
        ps0 += __shfl_xor_sync(0xffffffffu, ps0, 1); ps0 += __shfl_xor_sync(0xffffffffu, ps0, 2);
        pd0 += __shfl_xor_sync(0xffffffffu, pd0, 1); pd0 += __shfl_xor_sync(0xffffffffu, pd0, 2);
        ps1 += __shfl_xor_sync(0xffffffffu, ps1, 1); ps1 += __shfl_xor_sync(0xffffffffu, ps1, 2);
        pd1 += __shfl_xor_sync(0xffffffffu, pd1, 1); pd1 += __shfl_xor_sync(0xffffffffu, pd1, 2);
        if ((lane & 3) == 0) {
            int r0 = row0 + wm * 32 + mi * 16 + tr;
            if (r0 < M)     { g_as1[r0 * 4 + head] = ps0; g_ad1[r0 * 4 + head] = pd0; }
            if (r0 + 8 < M) { g_as1[(r0 + 8) * 4 + head] = ps1; g_ad1[(r0 + 8) * 4 + head] = pd1; }
        }
    }
}

// ---------------- GEMM2 (tensor core): h2 = h1a @ W2pad, fused attn2 ----------------
#define LDB 72
__global__ void __launch_bounds__(256) k_gemm2_tc(int M,
        const float* __restrict__ att_s, const float* __restrict__ att_d) {
    __shared__ __nv_bfloat16 Ah[128 * LDA], Al[128 * LDA];
    __shared__ __nv_bfloat16 Bh[32 * LDB],  Bl[32 * LDB];
    int tid = threadIdx.x;
    int warp = tid >> 5, lane = tid & 31;
    int wm = warp & 3, wn = warp >> 2;
    int row0 = blockIdx.x * 128;

    float acc[2][4][4];
#pragma unroll
    for (int mi = 0; mi < 2; mi++)
#pragma unroll
        for (int ni = 0; ni < 4; ni++)
#pragma unroll
            for (int k = 0; k < 4; k++) acc[mi][ni][k] = 0.f;

    int lrow = lane & 15, lcb = lane >> 4;

    for (int kt = 0; kt < 256; kt += 32) {
#pragma unroll
        for (int i = 0; i < 2; i++) {
            int v = tid + i * 256;
            int r = v >> 2, cv = (v & 3) * 8;
            int gr = row0 + r;
            uint4 vh, vl;
            if (gr < M) {
                vh = *(const uint4*)&g_h1ah[(size_t)gr * 256 + kt + cv];
                vl = *(const uint4*)&g_h1al[(size_t)gr * 256 + kt + cv];
            } else { vh = make_uint4(0,0,0,0); vl = vh; }
            *(uint4*)&Ah[r * LDA + cv] = vh;
            *(uint4*)&Al[r * LDA + cv] = vl;
        }
        {
            int r = tid >> 3, cv = (tid & 7) * 8;
            *(uint4*)&Bh[r * LDB + cv] = *(const uint4*)&g_w2h[(size_t)(kt + r) * 64 + cv];
            *(uint4*)&Bl[r * LDB + cv] = *(const uint4*)&g_w2l[(size_t)(kt + r) * 64 + cv];
        }
        __syncthreads();

#pragma unroll
        for (int ks = 0; ks < 32; ks += 16) {
            unsigned ah[2][4], al[2][4], bh[2][4], bl[2][4];
#pragma unroll
            for (int mi = 0; mi < 2; mi++) {
                unsigned ad = smem_u32(&Ah[(wm * 32 + mi * 16 + lrow) * LDA + ks + lcb * 8]);
                ldsm_x4(ad, ah[mi][0], ah[mi][1], ah[mi][2], ah[mi][3]);
                unsigned ad2 = smem_u32(&Al[(wm * 32 + mi * 16 + lrow) * LDA + ks + lcb * 8]);
                ldsm_x4(ad2, al[mi][0], al[mi][1], al[mi][2], al[mi][3]);
            }
#pragma unroll
            for (int nj = 0; nj < 2; nj++) {
                unsigned bd = smem_u32(&Bh[(ks + lrow) * LDB + wn * 32 + nj * 16 + lcb * 8]);
                ldsm_x4t(bd, bh[nj][0], bh[nj][1], bh[nj][2], bh[nj][3]);
                unsigned bd2 = smem_u32(&Bl[(ks + lrow) * LDB + wn * 32 + nj * 16 + lcb * 8]);
                ldsm_x4t(bd2, bl[nj][0], bl[nj][1], bl[nj][2], bl[nj][3]);
            }
#pragma unroll
            for (int mi = 0; mi < 2; mi++)
#pragma unroll
                for (int ni = 0; ni < 4; ni++) {
                    int nj = ni >> 1, s2 = (ni & 1) * 2;
                    mma_bf16(acc[mi][ni], ah[mi][0], ah[mi][1], ah[mi][2], ah[mi][3],
                             bh[nj][s2], bh[nj][s2 + 1]);
                    mma_bf16(acc[mi][ni], ah[mi][0], ah[mi][1], ah[mi][2], ah[mi][3],
                             bl[nj][s2], bl[nj][s2 + 1]);
                    mma_bf16(acc[mi][ni], al[mi][0], al[mi][1], al[mi][2], al[mi][3],
                             bh[nj][s2], bh[nj][s2 + 1]);
                }
        }
        __syncthreads();
    }

    int tr = lane >> 2, tc = (lane & 3) * 2;
#pragma unroll
    for (int mi = 0; mi < 2; mi++) {
        float ps0 = 0.f, pd0 = 0.f, ps1 = 0.f, pd1 = 0.f;
#pragma unroll
        for (int ni = 0; ni < 4; ni++) {
            int r = row0 + wm * 32 + mi * 16 + tr;
            int c = wn * 32 + ni * 8 + tc;
            if (c < 40) {
                if (r < M)
                    *(__half2*)&g_h2f[(size_t)r * 64 + c] = __floats2half2_rn(acc[mi][ni][0], acc[mi][ni][1]);
                if (r + 8 < M)
                    *(__half2*)&g_h2f[(size_t)(r + 8) * 64 + c] = __floats2half2_rn(acc[mi][ni][2], acc[mi][ni][3]);
                float s0 = __ldg(&att_s[c]), s1 = __ldg(&att_s[c + 1]);
                float d0 = __ldg(&att_d[c]), d1 = __ldg(&att_d[c + 1]);
                ps0 = fmaf(acc[mi][ni][0], s0, ps0); ps0 = fmaf(acc[mi][ni][1], s1, ps0);
                pd0 = fmaf(acc[mi][ni][0], d0, pd0); pd0 = fmaf(acc[mi][ni][1], d1, pd0);
                ps1 = fmaf(acc[mi][ni][2], s0, ps1); ps1 = fmaf(acc[mi][ni][3], s1, ps1);
                pd1 = fmaf(acc[mi][ni][2], d0, pd1); pd1 = fmaf(acc[mi][ni][3], d1, pd1);
            }
        }
        ps0 += __shfl_xor_sync(0xffffffffu, ps0, 1); ps0 += __shfl_xor_sync(0xffffffffu, ps0, 2);
        pd0 += __shfl_xor_sync(0xffffffffu, pd0, 1); pd0 += __shfl_xor_sync(0xffffffffu, pd0, 2);
        ps1 += __shfl_xor_sync(0xffffffffu, ps1, 1); ps1 += __shfl_xor_sync(0xffffffffu, ps1, 2);
        pd1 += __shfl_xor_sync(0xffffffffu, pd1, 1); pd1 += __shfl_xor_sync(0xffffffffu, pd1, 2);
        if ((lane & 3) == 0) {
            int r0 = row0 + wm * 32 + mi * 16 + tr;
            if (r0 < M)     { atomicAdd(&g_as2[r0], ps0); atomicAdd(&g_ad2[r0], pd0); }
            if (r0 + 8 < M) { atomicAdd(&g_as2[r0 + 8], ps1); atomicAdd(&g_ad2[r0 + 8], pd1); }
        }
    }
}

// ---------------- agg1: inline edge weights, fp16 gather, + bias + ELU, bf16-split out ----------------
__global__ void k_agg1(const float* __restrict__ bias, int M) {
    int w = (blockIdx.x * blockDim.x + threadIdx.x) >> 5;
    int lane = threadIdx.x & 31;
    if (w >= M) return;
    int start = g_off[w], end = g_off[w + 1];
    int hh = lane >> 3;
    int c0 = lane * 8;
    float4 adv = *(const float4*)&g_ad1[w * 4];
    float adh = (hh == 0) ? adv.x : (hh == 1) ? adv.y : (hh == 2) ? adv.z : adv.w;

    float acc[8] = {0.f, 0.f, 0.f, 0.f, 0.f, 0.f, 0.f, 0.f};
    float denom = 0.f;
    int j = start;
    for (; j + 1 < end; j += 2) {
        int s0 = g_csr[j], s1 = g_csr[j + 1];
        float e0 = g_as1[s0 * 4 + hh] + adh;
        float e1 = g_as1[s1 * 4 + hh] + adh;
        e0 = e0 > 0.f ? e0 : 0.2f * e0;
        e1 = e1 > 0.f ? e1 : 0.2f * e1;
        float w0 = __expf(e0), w1 = __expf(e1);
        uint4 q0 = *(const uint4*)&g_h1f[(size_t)s0 * 256 + c0];
        uint4 q1 = *(const uint4*)&g_h1f[(size_t)s1 * 256 + c0];
        denom += w0 + w1;
        const __half2* a = (const __half2*)&q0;
        const __half2* b = (const __half2*)&q1;
#pragma unroll
        for (int k = 0; k < 4; k++) {
            float2 fa = __half22float2(a[k]);
            float2 fb = __half22float2(b[k]);
            acc[2*k]   = fmaf(w0, fa.x, acc[2*k]);   acc[2*k]   = fmaf(w1, fb.x, acc[2*k]);
            acc[2*k+1] = fmaf(w0, fa.y, acc[2*k+1]); acc[2*k+1] = fmaf(w1, fb.y, acc[2*k+1]);
        }
    }
    if (j < end) {
        int s0 = g_csr[j];
        float e0 = g_as1[s0 * 4 + hh] + adh;
        e0 = e0 > 0.f ? e0 : 0.2f * e0;
        float w0 = __expf(e0);
        uint4 q0 = *(const uint4*)&g_h1f[(size_t)s0 * 256 + c0];
        denom += w0;
        const __half2* a = (const __half2*)&q0;
#pragma unroll
        for (int k = 0; k < 4; k++) {
            float2 fa = __half22float2(a[k]);
            acc[2*k]   = fmaf(w0, fa.x, acc[2*k]);
            acc[2*k+1] = fmaf(w0, fa.y, acc[2*k+1]);
        }
    }
    float inv = 1.f / denom;
    __nv_bfloat16 hi8[8], lo8[8];
#pragma unroll
    for (int k = 0; k < 8; k++) {
        float v = acc[k] * inv + bias[c0 + k];
        v = v > 0.f ? v : (__expf(v) - 1.f);   // ELU
        __nv_bfloat16 h = __float2bfloat16(v);
        hi8[k] = h;
        lo8[k] = __float2bfloat16(v - __bfloat162float(h));
    }
    *(uint4*)&g_h1ah[(size_t)w * 256 + c0] = *(const uint4*)hi8;
    *(uint4*)&g_h1al[(size_t)w * 256 + c0] = *(const uint4*)lo8;
}

// ---------------- agg2: inline edge weights, padded fp16 gather, final output ----------------
__global__ void k_agg2(const float* __restrict__ b2, float* __restrict__ out, int M) {
    int w = (blockIdx.x * blockDim.x + threadIdx.x) >> 5;
    int lane = threadIdx.x & 31;
    if (w >= M) return;
    int start = g_off[w], end = g_off[w + 1];
    float adv = g_ad2[w];
    bool val = lane < 20;
    float denom = 0.f, acc0 = 0.f, acc1 = 0.f;
    int j = start;
    for (; j + 1 < end; j += 2) {
        int s0 = g_csr[j], s1 = g_csr[j + 1];
        float e0 = g_as2[s0] + adv;
        float e1 = g_as2[s1] + adv;
        e0 = e0 > 0.f ? e0 : 0.2f * e0;
        e1 = e1 > 0.f ? e1 : 0.2f * e1;
        float w0 = __expf(e0), w1 = __expf(e1);
        float2 f0 = make_float2(0.f, 0.f), f1 = f0;
        if (val) {
            f0 = __half22float2(*(const __half2*)&g_h2f[(size_t)s0 * 64 + lane * 2]);
            f1 = __half22float2(*(const __half2*)&g_h2f[(size_t)s1 * 64 + lane * 2]);
        }
        denom += w0 + w1;
        acc0 = fmaf(w0, f0.x, acc0); acc0 = fmaf(w1, f1.x, acc0);
        acc1 = fmaf(w0, f0.y, acc1); acc1 = fmaf(w1, f1.y, acc1);
    }
    if (j < end) {
        int s0 = g_csr[j];
        float e0 = g_as2[s0] + adv;
        e0 = e0 > 0.f ? e0 : 0.2f * e0;
        float w0 = __expf(e0);
        float2 f0 = make_float2(0.f, 0.f);
        if (val) f0 = __half22float2(*(const __half2*)&g_h2f[(size_t)s0 * 64 + lane * 2]);
        denom += w0;
        acc0 = fmaf(w0, f0.x, acc0);
        acc1 = fmaf(w0, f0.y, acc1);
    }
    float inv = 1.f / denom;
    if (val) {
        out[(size_t)w * 40 + lane * 2]     = acc0 * inv + __ldg(&b2[lane * 2]);
        out[(size_t)w * 40 + lane * 2 + 1] = acc1 * inv + __ldg(&b2[lane * 2 + 1]);
    }
}

// ---------------- launch ----------------
extern "C" void kernel_launch(void* const* d_in, const int* in_sizes, int n_in,
                              void* d_out, int out_size) {
    const float* x    = (const float*)d_in[0];
    const void*  edge = (const void*)d_in[1];
    const float* W1   = (const float*)d_in[2];
    const float* as1  = (const float*)d_in[3];
    const float* ad1  = (const float*)d_in[4];
    const float* b1   = (const float*)d_in[5];
    const float* W2   = (const float*)d_in[6];
    const float* as2  = (const float*)d_in[7];
    const float* ad2  = (const float*)d_in[8];
    const float* b2   = (const float*)d_in[9];
    float* out = (float*)d_out;

    int N  = in_sizes[0] / 256;
    int E  = in_sizes[1] / 2;
    int ET = E + N;

    // 1) detect dtype + zero deg/as2/ad2
    k_detect<<<(N + 255) / 256, 256>>>((const int*)edge, E, N);

    // 2) fused: W splits + edge count
    int countBlocks = (ET + 255) / 256;
    k_split_count<<<SPLITB + countBlocks, 256>>>(W1, W2, edge, E, N);

    // 3) scan (needs count)
    k_scan_tiled<<<1, 1024>>>(N);

    // 4) GEMM1 + fused attn1 + appended scatter blocks (scatter needs scan)
    int rowBlocks = (N + 127) / 128;
    int scatterBlocks = (ET + 255) / 256;
    int extraY = (scatterBlocks + 1) / 2;
    k_gemm1_tc<<<dim3(2, rowBlocks + extraY), 256>>>(x, N, as1, ad1, edge, E, rowBlocks);

    // 5) agg1 (needs gemm1 + scatter)
    int warpGrid = (N * 32 + 255) / 256;
    k_agg1<<<warpGrid, 256>>>(b1, N);

    // 6) GEMM2 + fused attn2
    k_gemm2_tc<<<(N + 127) / 128, 256>>>(N, as2, ad2);

    // 7) agg2 -> output
    k_agg2<<<warpGrid, 256>>>(b2, out, N);
}